// round 12
// baseline (speedup 1.0000x reference)
#include <cuda_runtime.h>
#include <cstdint>
#include <cstddef>

#define BB 8
#define NN 16384
#define CC 64
#define SS 2048
#define KK 32

typedef unsigned long long ull;

// Scratch (device globals: no allocation allowed)
__device__ float g_feat1[(size_t)BB * NN * 64];   // features @ W1[3:67,:]
__device__ int   g_knn[(size_t)BB * SS * KK];     // top-32 neighbor indices

#define ADD2(r,a,b) asm("add.rn.f32x2 %0,%1,%2;" : "=l"(r) : "l"(a), "l"(b))
#define MUL2(r,a,b) asm("mul.rn.f32x2 %0,%1,%2;" : "=l"(r) : "l"(a), "l"(b))
#define FMA2(r,a,b,c) asm("fma.rn.f32x2 %0,%1,%2,%3;" : "=l"(r) : "l"(a), "l"(b), "l"(c))
#define PACK2(r,lo,hi) asm("mov.b64 %0,{%1,%2};" : "=l"(r) : "f"(lo), "f"(hi))
#define UNPACK2(lo,hi,v) asm("mov.b64 {%0,%1},%2;" : "=f"(lo), "=f"(hi) : "l"(v))

__device__ __forceinline__ uint32_t smem_u32(const void* p) {
    uint32_t a;
    asm("{ .reg .u64 t; cvta.to.shared.u64 t, %1; cvt.u32.u64 %0, t; }" : "=r"(a) : "l"(p));
    return a;
}
__device__ __forceinline__ uint32_t cluster_rank() {
    uint32_t r; asm("mov.u32 %0, %%cluster_ctarank;" : "=r"(r)); return r;
}
__device__ __forceinline__ void st_cluster_u64(uint32_t laddr, uint32_t rnk, ull v) {
    asm volatile("{ .reg .b32 ra; mapa.shared::cluster.u32 ra, %0, %1; "
                 "st.shared::cluster.u64 [ra], %2; }"
                 :: "r"(laddr), "r"(rnk), "l"(v) : "memory");
}
#define MBARRIER_INIT(a, cnt) \
    asm volatile("mbarrier.init.shared.b64 [%0], %1;" :: "r"(a), "r"((uint32_t)(cnt)) : "memory")
#define MBARRIER_ARRIVE_CLUSTER(a, rnk) \
    asm volatile("{ .reg .b32 ra; mapa.shared::cluster.u32 ra, %0, %1; " \
                 "mbarrier.arrive.shared::cluster.b64 _, [ra]; }" \
                 :: "r"(a), "r"((uint32_t)(rnk)) : "memory")
#define MBARRIER_WAIT_PARITY(a, par) do {                                   \
    uint32_t _m = (a), _p = (uint32_t)(par), _d;                            \
    asm volatile("{ .reg .pred p; "                                         \
        "mbarrier.try_wait.parity.acquire.cta.shared::cta.b64 p, [%1], %2; " \
        "selp.b32 %0, 1, 0, p; }" : "=r"(_d) : "r"(_m), "r"(_p) : "memory"); \
    if (!_d) {                                                              \
        asm volatile("{ .reg .pred P1; WL_%=: "                             \
            "mbarrier.try_wait.parity.acquire.cta.shared::cta.b64 P1, [%0], %1, 0x989680; " \
            "@P1 bra.uni WD_%=; bra.uni WL_%=; WD_%=: }"                    \
            :: "r"(_m), "r"(_p) : "memory");                                \
    }                                                                       \
} while (0)
#define CLUSTER_SYNC() do { \
    asm volatile("barrier.cluster.arrive.aligned;" ::: "memory"); \
    asm volatile("barrier.cluster.wait.aligned;" ::: "memory"); } while (0)

#define LDSV2(w0, w1, addr) \
    asm("ld.shared.v2.u64 {%0,%1}, [%2];" : "=l"(w0), "=l"(w1) : "r"(addr))

// depth-3 max tree over 8 u64 keys loaded as 4x ulonglong2
__device__ __forceinline__ ull max8_tree(const ull* k8) {
    const ulonglong2* rk = (const ulonglong2*)k8;
    ulonglong2 e0 = rk[0], e1 = rk[1], e2 = rk[2], e3 = rk[3];
    ull m0 = e0.x > e0.y ? e0.x : e0.y;
    ull m1 = e1.x > e1.y ? e1.x : e1.y;
    ull m2 = e2.x > e2.y ? e2.x : e2.y;
    ull m3 = e3.x > e3.y ? e3.x : e3.y;
    m0 = m0 > m1 ? m0 : m1;
    m2 = m2 > m3 ? m2 : m3;
    return m0 > m2 ? m0 : m2;
}

// ---------------------------------------------------------------------------
// Stage 1: FPS, 8-CTA cluster per batch — R9/R11-proven protocol; both 8-key
// folds (warp0 pre-push, everyone post-wait) are now depth-3 trees instead of
// 7-deep serial select chains (~30 cyc each off the critical path).
// Distance arithmetic bit-identical to R2..R11.
// ---------------------------------------------------------------------------
#define FPS_CTAS 8
#define FPS_PTS (NN / FPS_CTAS)   // 2048 per slice, 8 pts (4 pairs)/thread

__global__ __launch_bounds__(256, 1) __cluster_dims__(FPS_CTAS, 1, 1)
void fps_kernel(const float* __restrict__ xyz, float* __restrict__ newxyz)
{
    extern __shared__ float smf[];          // sx[NN] sy[NN] sz[NN] = 192KB
    float* sx = smf;
    float* sy = smf + NN;
    float* sz = smf + 2 * NN;
    __shared__ alignas(16) ull redk[8];
    __shared__ alignas(16) ull mbox[2][FPS_CTAS];
    __shared__ alignas(8) ull mbar;

    const unsigned rank = cluster_rank();
    const int b = blockIdx.x / FPS_CTAS;
    const int t = threadIdx.x;
    const int w = t >> 5, l = t & 31;
    const float* base = xyz + (size_t)b * NN * 3;
    for (int i = t; i < NN; i += 256) {
        sx[i] = base[3 * i + 0];
        sy[i] = base[3 * i + 1];
        sz[i] = base[3 * i + 2];
    }
    const uint32_t mbar_a = smem_u32(&mbar);
    if (t == 0) MBARRIER_INIT(mbar_a, FPS_CTAS);
    __syncthreads();
    CLUSTER_SYNC();

    const int pbase = rank * FPS_PTS;
    ull px[4], py[4], pz[4];
    float dist[8];
#pragma unroll
    for (int k = 0; k < 4; k++) {
        const int p = pbase + 2 * (t + 256 * k);
        px[k] = *(const ull*)(sx + p);
        py[k] = *(const ull*)(sy + p);
        pz[k] = *(const ull*)(sz + p);
        dist[2 * k] = 1e10f; dist[2 * k + 1] = 1e10f;
    }

    const uint32_t mbox_a = smem_u32(&mbox[0][rank]);
    float cx = sx[0], cy = sy[0], cz = sz[0];
    float* outp = newxyz + (size_t)b * SS * 3;

    for (int s = 0; s < SS; s++) {
        if (rank == 0 && t == 0) {
            outp[3 * s + 0] = cx; outp[3 * s + 1] = cy; outp[3 * s + 2] = cz;
        }
        ull ncx, ncy, ncz;
        {
            float mx0 = -cx, my0 = -cy, mz0 = -cz;
            PACK2(ncx, mx0, mx0); PACK2(ncy, my0, my0); PACK2(ncz, mz0, mz0);
        }
        float bv = -1.0f; int bi = 0;
#pragma unroll
        for (int k = 0; k < 4; k++) {
            ull dx, dy, dz, xx, yy, zz, s1, dd;
            ADD2(dx, px[k], ncx);
            ADD2(dy, py[k], ncy);
            ADD2(dz, pz[k], ncz);
            MUL2(xx, dx, dx);
            MUL2(yy, dy, dy);
            MUL2(zz, dz, dz);
            ADD2(s1, xx, yy);
            ADD2(dd, s1, zz);
            float d0, d1; UNPACK2(d0, d1, dd);
            float a0 = fminf(dist[2 * k], d0);     dist[2 * k] = a0;
            float a1 = fminf(dist[2 * k + 1], d1); dist[2 * k + 1] = a1;
            const int pl = 2 * (t + 256 * k);
            if (a0 > bv) { bv = a0; bi = pl; }
            if (a1 > bv) { bv = a1; bi = pl + 1; }
        }
        const int gbi = pbase + bi;                // global index
        const unsigned vb = __float_as_uint(bv);   // dist >= 0 -> bit-order ok
        const unsigned wv = __reduce_max_sync(0xffffffffu, vb);
        const unsigned cand = (vb == wv) ? (unsigned)~gbi : 0u;
        const unsigned wni = __reduce_max_sync(0xffffffffu, cand); // ~idx max = idx min
        if (l == 0) redk[w] = ((ull)wv << 32) | wni;
        __syncthreads();
        const int par = s & 1;
        if (w == 0) {
            const ull best = max8_tree(redk);      // depth-3 tree fold
            if (l < FPS_CTAS) {
                st_cluster_u64(mbox_a + par * (FPS_CTAS * 8), l, best);
                MBARRIER_ARRIVE_CLUSTER(mbar_a, l);
            }
        }
        MBARRIER_WAIT_PARITY(mbar_a, par);
        const ull bk = max8_tree(mbox[par]);       // depth-3 tree fold
        const unsigned widx = ~(unsigned)bk;
        cx = sx[widx]; cy = sy[widx]; cz = sz[widx];
    }
}

// ---------------------------------------------------------------------------
// Stage 2: 32 nearest neighbors per centroid, with the pregemm
// (feat1 = features @ W1[3:67,:]) folded in as a tail phase: after the last
// chunk's __syncthreads all scans are done, so sp is reused for W1 (16KB) and
// threads 0-127 each transform one of this block's 128 rows. Removes the
// standalone pregemm launch (40us serialized) for ~+10us inside this kernel.
// ---------------------------------------------------------------------------
#define CHUNK 8192
__global__ __launch_bounds__(512, 1) void knn_kernel(const float* __restrict__ xyz,
                                                     const float* __restrict__ newxyz,
                                                     const float* __restrict__ feat,
                                                     const float* __restrict__ W1)
{
    const int blk = blockIdx.x;
    const int b = blk >> 7;
    const int s0 = (blk & 127) * 16;
    extern __shared__ float4 sp[];
    const int tid = threadIdx.x, w = tid >> 5, l = tid & 31;
    const int srow = s0 + w;
    const float* q = newxyz + ((size_t)b * SS + srow) * 3;
    const float qx = q[0], qy = q[1], qz = q[2];
    const float q2 = __fadd_rn(__fadd_rn(__fmul_rn(qx, qx), __fmul_rn(qy, qy)),
                               __fmul_rn(qz, qz));
    unsigned val = 0, tau = 0;
    int idx = 0;
    const float* base = xyz + (size_t)b * NN * 3;

    for (int c = 0; c < 2; c++) {
        const int nb = c * CHUNK;
        for (int i = tid; i < CHUNK; i += 512) {
            const float x = base[3 * (nb + i) + 0];
            const float y = base[3 * (nb + i) + 1];
            const float z = base[3 * (nb + i) + 2];
            const float x2 = __fadd_rn(__fadd_rn(__fmul_rn(x, x), __fmul_rn(y, y)),
                                       __fmul_rn(z, z));
            sp[i] = make_float4(x, y, z, x2);
        }
        __syncthreads();

        int n0 = 0;
        if (c == 0) {
            float4 p = sp[l];
            float cross = __fmaf_rn(p.z, qz, __fmaf_rn(p.y, qy, __fmul_rn(p.x, qx)));
            float d = __fmaf_rn(-2.f, cross, __fadd_rn(q2, p.w));
            unsigned bb = __float_as_uint(d);
            val = bb ^ (unsigned)(((int)bb >> 31) | 0x80000000);
            idx = l;
            tau = __reduce_max_sync(0xffffffffu, val);
            n0 = 32;
        }
        for (; n0 < CHUNK; n0 += 32) {
            float4 p = sp[n0 + l];
            float cross = __fmaf_rn(p.z, qz, __fmaf_rn(p.y, qy, __fmul_rn(p.x, qx)));
            float d = __fmaf_rn(-2.f, cross, __fadd_rn(q2, p.w));
            unsigned bb = __float_as_uint(d);
            unsigned du = bb ^ (unsigned)(((int)bb >> 31) | 0x80000000);
            unsigned want = __ballot_sync(0xffffffffu, du < tau);
            while (want) {
                const int leader = __ffs(want) - 1;
                want &= (want - 1);
                unsigned cb = __shfl_sync(0xffffffffu, du, leader);
                if (cb < tau) {
                    unsigned rm = __ballot_sync(0xffffffffu, val == tau);
                    const int r = __ffs(rm) - 1;
                    if (l == r) { val = cb; idx = nb + n0 + leader; }
                    tau = __reduce_max_sync(0xffffffffu, val);
                }
            }
        }
        __syncthreads();   // after last iter: ALL scans of sp complete
    }
    g_knn[((size_t)b * SS + srow) * KK + l] = idx;

    // --- pregemm tail: this block owns rows [blk*128, blk*128+128) ---
    float* sw = (float*)sp;   // 64*64 floats = 16KB, sp no longer needed
    for (int i = tid; i < 64 * 64; i += 512) sw[i] = W1[192 + i];
    __syncthreads();
    if (tid < 128) {
        const size_t row = (size_t)blk * 128 + tid;
        const float4* f4 = (const float4*)(feat + row * 64);
        float acc[64];
#pragma unroll
        for (int j = 0; j < 64; j++) acc[j] = 0.f;
        for (int i4 = 0; i4 < 16; i4++) {
            float4 fv = f4[i4];
            const float4* w0 = (const float4*)(sw + (i4 * 4 + 0) * 64);
            const float4* w1 = (const float4*)(sw + (i4 * 4 + 1) * 64);
            const float4* w2 = (const float4*)(sw + (i4 * 4 + 2) * 64);
            const float4* w3 = (const float4*)(sw + (i4 * 4 + 3) * 64);
#pragma unroll
            for (int jv = 0; jv < 16; jv++) {
                float4 a0 = w0[jv], a1 = w1[jv], a2 = w2[jv], a3 = w3[jv];
                acc[jv * 4 + 0] = fmaf(fv.x, a0.x, fmaf(fv.y, a1.x, fmaf(fv.z, a2.x, fmaf(fv.w, a3.x, acc[jv * 4 + 0]))));
                acc[jv * 4 + 1] = fmaf(fv.x, a0.y, fmaf(fv.y, a1.y, fmaf(fv.z, a2.y, fmaf(fv.w, a3.y, acc[jv * 4 + 1]))));
                acc[jv * 4 + 2] = fmaf(fv.x, a0.z, fmaf(fv.y, a1.z, fmaf(fv.z, a2.z, fmaf(fv.w, a3.z, acc[jv * 4 + 2]))));
                acc[jv * 4 + 3] = fmaf(fv.x, a0.w, fmaf(fv.y, a1.w, fmaf(fv.z, a2.w, fmaf(fv.w, a3.w, acc[jv * 4 + 3]))));
            }
        }
        float4* o4 = (float4*)(g_feat1 + row * 64);
#pragma unroll
        for (int jv = 0; jv < 16; jv++)
            o4[jv] = make_float4(acc[jv * 4], acc[jv * 4 + 1], acc[jv * 4 + 2], acc[jv * 4 + 3]);
    }
}

// ---------------------------------------------------------------------------
// Stage 4: gather + MLP + max over K — R10-proven outer-product tiling, now
// PERSISTENT: 296 blocks (2/SM), each loops over centroid-groups so weights
// load + __syncthreads happen once per block instead of once per group.
// Body has no block-level syncs (hb is warp-private).
// ---------------------------------------------------------------------------
#define MLP_GRID 296
__global__ __launch_bounds__(256, 2) void mlp_kernel(const float* __restrict__ xyz,
                                                     const float* __restrict__ newxyz,
                                                     const float* __restrict__ W1,
                                                     const float* __restrict__ b1,
                                                     const float* __restrict__ W2,
                                                     const float* __restrict__ b2,
                                                     const float* __restrict__ W3,
                                                     const float* __restrict__ b3,
                                                     float* __restrict__ outfeat)
{
    extern __shared__ float smf2[];
    float* sW2 = smf2;             // 64*64
    float* sW3 = smf2 + 4096;      // 64*128
    float* hbuf = smf2 + 12288;    // 8 warps * 2048

    const int tid = threadIdx.x;
    for (int i = tid; i < 4096; i += 256) sW2[i] = W2[i];
    for (int i = tid; i < 8192; i += 256) sW3[i] = W3[i];
    __syncthreads();

    const int w = tid >> 5, l = tid & 31;
    const int a = l >> 3;          // neighbor group (0..3)
    const int bc = l & 7;          // column group (0..7)
    float* hb = hbuf + w * 2048;
    const uint32_t w2a = smem_u32(sW2);
    const uint32_t w3a = smem_u32(sW3);

#define OPROW(hval, base) do { ull hx_; PACK2(hx_, hval, hval);            \
        FMA2(acc[(base) + 0], hx_, w0_, acc[(base) + 0]);                   \
        FMA2(acc[(base) + 1], hx_, w1_, acc[(base) + 1]);                   \
        FMA2(acc[(base) + 2], hx_, w2_, acc[(base) + 2]);                   \
        FMA2(acc[(base) + 3], hx_, w3_, acc[(base) + 3]); } while (0)

    for (int g = blockIdx.x; g < BB * SS / 8; g += MLP_GRID) {
        const int c = g * 8 + w;
        const int b = c / SS;

        const int nb = g_knn[(size_t)c * KK + l];
        const float* p = xyz + ((size_t)b * NN + nb) * 3;
        const float px = p[0], py = p[1], pz = p[2];
        const float* q = newxyz + (size_t)c * 3;
        const float dx = px - q[0], dy = py - q[1], dz = pz - q[2];
        const float4* fg = (const float4*)(g_feat1 + ((size_t)b * NN + nb) * 64);

        // layer 1
#pragma unroll
        for (int jv = 0; jv < 16; jv++) {
            float4 f = fg[jv];
            float4 bb = __ldg((const float4*)b1 + jv);
            float4 u0 = __ldg((const float4*)(W1) + jv);
            float4 u1 = __ldg((const float4*)(W1 + 64) + jv);
            float4 u2 = __ldg((const float4*)(W1 + 128) + jv);
            hb[(jv * 4 + 0) * 32 + l] = fmaxf(fmaf(dz, u2.x, fmaf(dy, u1.x, fmaf(dx, u0.x, f.x + bb.x))), 0.f);
            hb[(jv * 4 + 1) * 32 + l] = fmaxf(fmaf(dz, u2.y, fmaf(dy, u1.y, fmaf(dx, u0.y, f.y + bb.y))), 0.f);
            hb[(jv * 4 + 2) * 32 + l] = fmaxf(fmaf(dz, u2.z, fmaf(dy, u1.z, fmaf(dx, u0.z, f.z + bb.z))), 0.f);
            hb[(jv * 4 + 3) * 32 + l] = fmaxf(fmaf(dz, u2.w, fmaf(dy, u1.w, fmaf(dx, u0.w, f.w + bb.w))), 0.f);
        }
        __syncwarp();

        // layer 2: tile 8n x 8j
        {
            ull acc[32];
            const ull* b2u = (const ull*)b2;
#pragma unroll
            for (int jp = 0; jp < 4; jp++) {
                const ull bb = __ldg(b2u + 4 * bc + jp);
#pragma unroll
                for (int n = 0; n < 8; n++) acc[n * 4 + jp] = bb;
            }
            for (int i = 0; i < 64; i++) {
                float4 h0 = *(const float4*)(hb + i * 32 + a * 8);
                float4 h1 = *(const float4*)(hb + i * 32 + a * 8 + 4);
                ull w0_, w1_, w2_, w3_;
                LDSV2(w0_, w1_, w2a + i * 256 + bc * 32);
                LDSV2(w2_, w3_, w2a + i * 256 + bc * 32 + 16);
                OPROW(h0.x, 0);  OPROW(h0.y, 4);  OPROW(h0.z, 8);  OPROW(h0.w, 12);
                OPROW(h1.x, 16); OPROW(h1.y, 20); OPROW(h1.z, 24); OPROW(h1.w, 28);
            }
            __syncwarp();
#pragma unroll
            for (int jp = 0; jp < 4; jp++) {
                float vlo[8], vhi[8];
#pragma unroll
                for (int n = 0; n < 8; n++) {
                    float lo, hi; UNPACK2(lo, hi, acc[n * 4 + jp]);
                    vlo[n] = fmaxf(lo, 0.f); vhi[n] = fmaxf(hi, 0.f);
                }
                const int j0 = 8 * bc + 2 * jp;
                *(float4*)(hb + j0 * 32 + a * 8)       = make_float4(vlo[0], vlo[1], vlo[2], vlo[3]);
                *(float4*)(hb + j0 * 32 + a * 8 + 4)   = make_float4(vlo[4], vlo[5], vlo[6], vlo[7]);
                *(float4*)(hb + (j0 + 1) * 32 + a * 8)     = make_float4(vhi[0], vhi[1], vhi[2], vhi[3]);
                *(float4*)(hb + (j0 + 1) * 32 + a * 8 + 4) = make_float4(vhi[4], vhi[5], vhi[6], vhi[7]);
            }
            __syncwarp();
        }

        // layer 3 (two 64-col halves) + relu + max over K
        float* of = outfeat + (size_t)c * 128;
        const ull* b3u = (const ull*)b3;
#pragma unroll 1
        for (int h = 0; h < 2; h++) {
            ull acc[32];
#pragma unroll
            for (int jp = 0; jp < 4; jp++) {
                const ull bb = __ldg(b3u + h * 32 + 4 * bc + jp);
#pragma unroll
                for (int n = 0; n < 8; n++) acc[n * 4 + jp] = bb;
            }
            for (int i = 0; i < 64; i++) {
                float4 h0 = *(const float4*)(hb + i * 32 + a * 8);
                float4 h1 = *(const float4*)(hb + i * 32 + a * 8 + 4);
                ull w0_, w1_, w2_, w3_;
                LDSV2(w0_, w1_, w3a + i * 512 + h * 256 + bc * 32);
                LDSV2(w2_, w3_, w3a + i * 512 + h * 256 + bc * 32 + 16);
                OPROW(h0.x, 0);  OPROW(h0.y, 4);  OPROW(h0.z, 8);  OPROW(h0.w, 12);
                OPROW(h1.x, 16); OPROW(h1.y, 20); OPROW(h1.z, 24); OPROW(h1.w, 28);
            }
            float cm[8];
#pragma unroll
            for (int jp = 0; jp < 4; jp++) {
                float mlo = 0.f, mhi = 0.f;
#pragma unroll
                for (int n = 0; n < 8; n++) {
                    float lo, hi; UNPACK2(lo, hi, acc[n * 4 + jp]);
                    mlo = fmaxf(mlo, lo); mhi = fmaxf(mhi, hi);
                }
                cm[2 * jp] = mlo; cm[2 * jp + 1] = mhi;
            }
#pragma unroll
            for (int jj = 0; jj < 8; jj++) {
                cm[jj] = fmaxf(cm[jj], __shfl_xor_sync(0xffffffffu, cm[jj], 8));
                cm[jj] = fmaxf(cm[jj], __shfl_xor_sync(0xffffffffu, cm[jj], 16));
            }
            if (a == 0) {
                *(float4*)(of + h * 64 + bc * 8)     = make_float4(cm[0], cm[1], cm[2], cm[3]);
                *(float4*)(of + h * 64 + bc * 8 + 4) = make_float4(cm[4], cm[5], cm[6], cm[7]);
            }
        }
        __syncwarp();
    }
#undef OPROW
}

// ---------------------------------------------------------------------------
extern "C" void kernel_launch(void* const* d_in, const int* in_sizes, int n_in,
                              void* d_out, int out_size)
{
    (void)in_sizes; (void)n_in; (void)out_size;
    const float* xyz  = (const float*)d_in[0];
    const float* feat = (const float*)d_in[1];
    const float* W1   = (const float*)d_in[2];
    const float* b1   = (const float*)d_in[3];
    const float* W2   = (const float*)d_in[4];
    const float* b2   = (const float*)d_in[5];
    const float* W3   = (const float*)d_in[6];
    const float* b3   = (const float*)d_in[7];

    float* newxyz  = (float*)d_out;                       // [B,S,3]
    float* outfeat = newxyz + (size_t)BB * SS * 3;        // [B,S,128]

    cudaFuncSetAttribute(fps_kernel, cudaFuncAttributeMaxDynamicSharedMemorySize, 3 * NN * 4);
    cudaFuncSetAttribute(knn_kernel, cudaFuncAttributeMaxDynamicSharedMemorySize, CHUNK * 16);
    cudaFuncSetAttribute(mlp_kernel, cudaFuncAttributeMaxDynamicSharedMemorySize, 114688);

    fps_kernel<<<BB * FPS_CTAS, 256, 3 * NN * 4>>>(xyz, newxyz);
    knn_kernel<<<BB * SS / 16, 512, CHUNK * 16>>>(xyz, newxyz, feat, W1);
    mlp_kernel<<<MLP_GRID, 256, 114688>>>(xyz, newxyz, W1, b1, W2, b2, W3, b3, outfeat);
}

// round 13
// speedup vs baseline: 1.0078x; 1.0078x over previous
#include <cuda_runtime.h>
#include <cstdint>
#include <cstddef>

#define BB 8
#define NN 16384
#define CC 64
#define SS 2048
#define KK 32

typedef unsigned long long ull;

// Scratch (device globals: no allocation allowed)
__device__ float g_feat1[(size_t)BB * NN * 64];   // features @ W1[3:67,:]
__device__ int   g_knn[(size_t)BB * SS * KK];     // top-32 neighbor indices

#define ADD2(r,a,b) asm("add.rn.f32x2 %0,%1,%2;" : "=l"(r) : "l"(a), "l"(b))
#define MUL2(r,a,b) asm("mul.rn.f32x2 %0,%1,%2;" : "=l"(r) : "l"(a), "l"(b))
#define FMA2(r,a,b,c) asm("fma.rn.f32x2 %0,%1,%2,%3;" : "=l"(r) : "l"(a), "l"(b), "l"(c))
#define PACK2(r,lo,hi) asm("mov.b64 %0,{%1,%2};" : "=l"(r) : "f"(lo), "f"(hi))
#define UNPACK2(lo,hi,v) asm("mov.b64 {%0,%1},%2;" : "=f"(lo), "=f"(hi) : "l"(v))

__device__ __forceinline__ uint32_t smem_u32(const void* p) {
    uint32_t a;
    asm("{ .reg .u64 t; cvta.to.shared.u64 t, %1; cvt.u32.u64 %0, t; }" : "=r"(a) : "l"(p));
    return a;
}
__device__ __forceinline__ uint32_t cluster_rank() {
    uint32_t r; asm("mov.u32 %0, %%cluster_ctarank;" : "=r"(r)); return r;
}
__device__ __forceinline__ void st_cluster_u64(uint32_t laddr, uint32_t rnk, ull v) {
    asm volatile("{ .reg .b32 ra; mapa.shared::cluster.u32 ra, %0, %1; "
                 "st.shared::cluster.u64 [ra], %2; }"
                 :: "r"(laddr), "r"(rnk), "l"(v) : "memory");
}
#define MBARRIER_INIT(a, cnt) \
    asm volatile("mbarrier.init.shared.b64 [%0], %1;" :: "r"(a), "r"((uint32_t)(cnt)) : "memory")
#define MBARRIER_ARRIVE_CLUSTER(a, rnk) \
    asm volatile("{ .reg .b32 ra; mapa.shared::cluster.u32 ra, %0, %1; " \
                 "mbarrier.arrive.shared::cluster.b64 _, [ra]; }" \
                 :: "r"(a), "r"((uint32_t)(rnk)) : "memory")
#define MBARRIER_WAIT_PARITY(a, par) do {                                   \
    uint32_t _m = (a), _p = (uint32_t)(par), _d;                            \
    asm volatile("{ .reg .pred p; "                                         \
        "mbarrier.try_wait.parity.acquire.cta.shared::cta.b64 p, [%1], %2; " \
        "selp.b32 %0, 1, 0, p; }" : "=r"(_d) : "r"(_m), "r"(_p) : "memory"); \
    if (!_d) {                                                              \
        asm volatile("{ .reg .pred P1; WL_%=: "                             \
            "mbarrier.try_wait.parity.acquire.cta.shared::cta.b64 P1, [%0], %1, 0x989680; " \
            "@P1 bra.uni WD_%=; bra.uni WL_%=; WD_%=: }"                    \
            :: "r"(_m), "r"(_p) : "memory");                                \
    }                                                                       \
} while (0)
#define CLUSTER_SYNC() do { \
    asm volatile("barrier.cluster.arrive.aligned;" ::: "memory"); \
    asm volatile("barrier.cluster.wait.aligned;" ::: "memory"); } while (0)

#define LDSV2(w0, w1, addr) \
    asm("ld.shared.v2.u64 {%0,%1}, [%2];" : "=l"(w0), "=l"(w1) : "r"(addr))

// depth-3 max tree over 8 u64 keys loaded as 4x ulonglong2
__device__ __forceinline__ ull max8_tree(const ull* k8) {
    const ulonglong2* rk = (const ulonglong2*)k8;
    ulonglong2 e0 = rk[0], e1 = rk[1], e2 = rk[2], e3 = rk[3];
    ull m0 = e0.x > e0.y ? e0.x : e0.y;
    ull m1 = e1.x > e1.y ? e1.x : e1.y;
    ull m2 = e2.x > e2.y ? e2.x : e2.y;
    ull m3 = e3.x > e3.y ? e3.x : e3.y;
    m0 = m0 > m1 ? m0 : m1;
    m2 = m2 > m3 ? m2 : m3;
    return m0 > m2 ? m0 : m2;
}

// ---------------------------------------------------------------------------
// Stage 1: FPS, 8-CTA cluster per batch — R12-measured form (885.9us):
// select-chain argmax during compute, REDUX pair, one BAR, warp0 tree-folds
// 8 keys and pushes the CTA-best key to all 8 ranks, cta-scope acquire wait,
// everyone tree-folds the 8 mailbox keys, local coord lookup.
// Distance arithmetic bit-identical to R2..R12.
// ---------------------------------------------------------------------------
#define FPS_CTAS 8
#define FPS_PTS (NN / FPS_CTAS)   // 2048 per slice, 8 pts (4 pairs)/thread

__global__ __launch_bounds__(256, 1) __cluster_dims__(FPS_CTAS, 1, 1)
void fps_kernel(const float* __restrict__ xyz, float* __restrict__ newxyz)
{
    extern __shared__ float smf[];          // sx[NN] sy[NN] sz[NN] = 192KB
    float* sx = smf;
    float* sy = smf + NN;
    float* sz = smf + 2 * NN;
    __shared__ alignas(16) ull redk[8];
    __shared__ alignas(16) ull mbox[2][FPS_CTAS];
    __shared__ alignas(8) ull mbar;

    const unsigned rank = cluster_rank();
    const int b = blockIdx.x / FPS_CTAS;
    const int t = threadIdx.x;
    const int w = t >> 5, l = t & 31;
    const float* base = xyz + (size_t)b * NN * 3;
    for (int i = t; i < NN; i += 256) {
        sx[i] = base[3 * i + 0];
        sy[i] = base[3 * i + 1];
        sz[i] = base[3 * i + 2];
    }
    const uint32_t mbar_a = smem_u32(&mbar);
    if (t == 0) MBARRIER_INIT(mbar_a, FPS_CTAS);
    __syncthreads();
    CLUSTER_SYNC();

    const int pbase = rank * FPS_PTS;
    ull px[4], py[4], pz[4];
    float dist[8];
#pragma unroll
    for (int k = 0; k < 4; k++) {
        const int p = pbase + 2 * (t + 256 * k);
        px[k] = *(const ull*)(sx + p);
        py[k] = *(const ull*)(sy + p);
        pz[k] = *(const ull*)(sz + p);
        dist[2 * k] = 1e10f; dist[2 * k + 1] = 1e10f;
    }

    const uint32_t mbox_a = smem_u32(&mbox[0][rank]);
    float cx = sx[0], cy = sy[0], cz = sz[0];
    float* outp = newxyz + (size_t)b * SS * 3;

    for (int s = 0; s < SS; s++) {
        if (rank == 0 && t == 0) {
            outp[3 * s + 0] = cx; outp[3 * s + 1] = cy; outp[3 * s + 2] = cz;
        }
        ull ncx, ncy, ncz;
        {
            float mx0 = -cx, my0 = -cy, mz0 = -cz;
            PACK2(ncx, mx0, mx0); PACK2(ncy, my0, my0); PACK2(ncz, mz0, mz0);
        }
        float bv = -1.0f; int bi = 0;
#pragma unroll
        for (int k = 0; k < 4; k++) {
            ull dx, dy, dz, xx, yy, zz, s1, dd;
            ADD2(dx, px[k], ncx);
            ADD2(dy, py[k], ncy);
            ADD2(dz, pz[k], ncz);
            MUL2(xx, dx, dx);
            MUL2(yy, dy, dy);
            MUL2(zz, dz, dz);
            ADD2(s1, xx, yy);
            ADD2(dd, s1, zz);
            float d0, d1; UNPACK2(d0, d1, dd);
            float a0 = fminf(dist[2 * k], d0);     dist[2 * k] = a0;
            float a1 = fminf(dist[2 * k + 1], d1); dist[2 * k + 1] = a1;
            const int pl = 2 * (t + 256 * k);
            if (a0 > bv) { bv = a0; bi = pl; }
            if (a1 > bv) { bv = a1; bi = pl + 1; }
        }
        const int gbi = pbase + bi;                // global index
        const unsigned vb = __float_as_uint(bv);   // dist >= 0 -> bit-order ok
        const unsigned wv = __reduce_max_sync(0xffffffffu, vb);
        const unsigned cand = (vb == wv) ? (unsigned)~gbi : 0u;
        const unsigned wni = __reduce_max_sync(0xffffffffu, cand); // ~idx max = idx min
        if (l == 0) redk[w] = ((ull)wv << 32) | wni;
        __syncthreads();
        const int par = s & 1;
        if (w == 0) {
            const ull best = max8_tree(redk);      // depth-3 tree fold
            if (l < FPS_CTAS) {
                st_cluster_u64(mbox_a + par * (FPS_CTAS * 8), l, best);
                MBARRIER_ARRIVE_CLUSTER(mbar_a, l);
            }
        }
        MBARRIER_WAIT_PARITY(mbar_a, par);
        const ull bk = max8_tree(mbox[par]);       // depth-3 tree fold
        const unsigned widx = ~(unsigned)bk;
        cx = sx[widx]; cy = sy[widx]; cz = sz[widx];
    }
}

// ---------------------------------------------------------------------------
// Stage 2: 32 nearest neighbors per centroid (R11-proven form, unfused).
// ---------------------------------------------------------------------------
#define CHUNK 8192
__global__ __launch_bounds__(512, 1) void knn_kernel(const float* __restrict__ xyz,
                                                     const float* __restrict__ newxyz)
{
    const int blk = blockIdx.x;
    const int b = blk >> 7;
    const int s0 = (blk & 127) * 16;
    extern __shared__ float4 sp[];
    const int tid = threadIdx.x, w = tid >> 5, l = tid & 31;
    const int srow = s0 + w;
    const float* q = newxyz + ((size_t)b * SS + srow) * 3;
    const float qx = q[0], qy = q[1], qz = q[2];
    const float q2 = __fadd_rn(__fadd_rn(__fmul_rn(qx, qx), __fmul_rn(qy, qy)),
                               __fmul_rn(qz, qz));
    unsigned val = 0, tau = 0;
    int idx = 0;
    const float* base = xyz + (size_t)b * NN * 3;

    for (int c = 0; c < 2; c++) {
        const int nb = c * CHUNK;
        for (int i = tid; i < CHUNK; i += 512) {
            const float x = base[3 * (nb + i) + 0];
            const float y = base[3 * (nb + i) + 1];
            const float z = base[3 * (nb + i) + 2];
            const float x2 = __fadd_rn(__fadd_rn(__fmul_rn(x, x), __fmul_rn(y, y)),
                                       __fmul_rn(z, z));
            sp[i] = make_float4(x, y, z, x2);
        }
        __syncthreads();

        int n0 = 0;
        if (c == 0) {
            float4 p = sp[l];
            float cross = __fmaf_rn(p.z, qz, __fmaf_rn(p.y, qy, __fmul_rn(p.x, qx)));
            float d = __fmaf_rn(-2.f, cross, __fadd_rn(q2, p.w));
            unsigned bb = __float_as_uint(d);
            val = bb ^ (unsigned)(((int)bb >> 31) | 0x80000000);
            idx = l;
            tau = __reduce_max_sync(0xffffffffu, val);
            n0 = 32;
        }
        for (; n0 < CHUNK; n0 += 32) {
            float4 p = sp[n0 + l];
            float cross = __fmaf_rn(p.z, qz, __fmaf_rn(p.y, qy, __fmul_rn(p.x, qx)));
            float d = __fmaf_rn(-2.f, cross, __fadd_rn(q2, p.w));
            unsigned bb = __float_as_uint(d);
            unsigned du = bb ^ (unsigned)(((int)bb >> 31) | 0x80000000);
            unsigned want = __ballot_sync(0xffffffffu, du < tau);
            while (want) {
                const int leader = __ffs(want) - 1;
                want &= (want - 1);
                unsigned cb = __shfl_sync(0xffffffffu, du, leader);
                if (cb < tau) {
                    unsigned rm = __ballot_sync(0xffffffffu, val == tau);
                    const int r = __ffs(rm) - 1;
                    if (l == r) { val = cb; idx = nb + n0 + leader; }
                    tau = __reduce_max_sync(0xffffffffu, val);
                }
            }
        }
        __syncthreads();
    }
    g_knn[((size_t)b * SS + srow) * KK + l] = idx;
}

// ---------------------------------------------------------------------------
// Stage 3: per-point pre-transform feat1 = features @ W1[3:67,:]
// (standalone again — the R12 fusion regressed).
// ---------------------------------------------------------------------------
__global__ __launch_bounds__(256, 1) void pregemm_kernel(const float* __restrict__ feat,
                                                         const float* __restrict__ W1)
{
    __shared__ float sw[64 * 64];
    for (int i = threadIdx.x; i < 64 * 64; i += 256) sw[i] = W1[192 + i];
    __syncthreads();
    const int row = blockIdx.x * 256 + threadIdx.x;
    const float4* f4 = (const float4*)(feat + (size_t)row * 64);
    float acc[64];
#pragma unroll
    for (int j = 0; j < 64; j++) acc[j] = 0.f;
    for (int i4 = 0; i4 < 16; i4++) {
        float4 fv = f4[i4];
        const float4* w0 = (const float4*)(sw + (i4 * 4 + 0) * 64);
        const float4* w1 = (const float4*)(sw + (i4 * 4 + 1) * 64);
        const float4* w2 = (const float4*)(sw + (i4 * 4 + 2) * 64);
        const float4* w3 = (const float4*)(sw + (i4 * 4 + 3) * 64);
#pragma unroll
        for (int jv = 0; jv < 16; jv++) {
            float4 a0 = w0[jv], a1 = w1[jv], a2 = w2[jv], a3 = w3[jv];
            acc[jv * 4 + 0] = fmaf(fv.x, a0.x, fmaf(fv.y, a1.x, fmaf(fv.z, a2.x, fmaf(fv.w, a3.x, acc[jv * 4 + 0]))));
            acc[jv * 4 + 1] = fmaf(fv.x, a0.y, fmaf(fv.y, a1.y, fmaf(fv.z, a2.y, fmaf(fv.w, a3.y, acc[jv * 4 + 1]))));
            acc[jv * 4 + 2] = fmaf(fv.x, a0.z, fmaf(fv.y, a1.z, fmaf(fv.z, a2.z, fmaf(fv.w, a3.z, acc[jv * 4 + 2]))));
            acc[jv * 4 + 3] = fmaf(fv.x, a0.w, fmaf(fv.y, a1.w, fmaf(fv.z, a2.w, fmaf(fv.w, a3.w, acc[jv * 4 + 3]))));
        }
    }
    float4* o4 = (float4*)(g_feat1 + (size_t)row * 64);
#pragma unroll
    for (int jv = 0; jv < 16; jv++)
        o4[jv] = make_float4(acc[jv * 4], acc[jv * 4 + 1], acc[jv * 4 + 2], acc[jv * 4 + 3]);
}

// ---------------------------------------------------------------------------
// Stage 4: gather + MLP + max over K — R10/R11-measured form (359us):
// outer-product tiling, one block per 8 centroids (non-persistent).
// ---------------------------------------------------------------------------
__global__ __launch_bounds__(256, 2) void mlp_kernel(const float* __restrict__ xyz,
                                                     const float* __restrict__ newxyz,
                                                     const float* __restrict__ W1,
                                                     const float* __restrict__ b1,
                                                     const float* __restrict__ W2,
                                                     const float* __restrict__ b2,
                                                     const float* __restrict__ W3,
                                                     const float* __restrict__ b3,
                                                     float* __restrict__ outfeat)
{
    extern __shared__ float smf2[];
    float* sW2 = smf2;             // 64*64
    float* sW3 = smf2 + 4096;      // 64*128
    float* hbuf = smf2 + 12288;    // 8 warps * 2048

    const int tid = threadIdx.x;
    for (int i = tid; i < 4096; i += 256) sW2[i] = W2[i];
    for (int i = tid; i < 8192; i += 256) sW3[i] = W3[i];
    __syncthreads();

    const int w = tid >> 5, l = tid & 31;
    const int a = l >> 3;          // neighbor group (0..3)
    const int bc = l & 7;          // column group (0..7)
    const int c = blockIdx.x * 8 + w;
    const int b = c / SS;
    float* hb = hbuf + w * 2048;
    const uint32_t w2a = smem_u32(sW2);
    const uint32_t w3a = smem_u32(sW3);

    const int nb = g_knn[(size_t)c * KK + l];
    const float* p = xyz + ((size_t)b * NN + nb) * 3;
    const float px = p[0], py = p[1], pz = p[2];
    const float* q = newxyz + (size_t)c * 3;
    const float dx = px - q[0], dy = py - q[1], dz = pz - q[2];
    const float4* fg = (const float4*)(g_feat1 + ((size_t)b * NN + nb) * 64);

    // layer 1: feat1(gathered) + xyz_norm @ W1[0:3] + b1, relu -> hb[ch*32+l]
#pragma unroll
    for (int jv = 0; jv < 16; jv++) {
        float4 f = fg[jv];
        float4 bb = __ldg((const float4*)b1 + jv);
        float4 u0 = __ldg((const float4*)(W1) + jv);
        float4 u1 = __ldg((const float4*)(W1 + 64) + jv);
        float4 u2 = __ldg((const float4*)(W1 + 128) + jv);
        hb[(jv * 4 + 0) * 32 + l] = fmaxf(fmaf(dz, u2.x, fmaf(dy, u1.x, fmaf(dx, u0.x, f.x + bb.x))), 0.f);
        hb[(jv * 4 + 1) * 32 + l] = fmaxf(fmaf(dz, u2.y, fmaf(dy, u1.y, fmaf(dx, u0.y, f.y + bb.y))), 0.f);
        hb[(jv * 4 + 2) * 32 + l] = fmaxf(fmaf(dz, u2.z, fmaf(dy, u1.z, fmaf(dx, u0.z, f.z + bb.z))), 0.f);
        hb[(jv * 4 + 3) * 32 + l] = fmaxf(fmaf(dz, u2.w, fmaf(dy, u1.w, fmaf(dx, u0.w, f.w + bb.w))), 0.f);
    }
    __syncwarp();

#define OPROW(hval, base) do { ull hx_; PACK2(hx_, hval, hval);            \
        FMA2(acc[(base) + 0], hx_, w0_, acc[(base) + 0]);                   \
        FMA2(acc[(base) + 1], hx_, w1_, acc[(base) + 1]);                   \
        FMA2(acc[(base) + 2], hx_, w2_, acc[(base) + 2]);                   \
        FMA2(acc[(base) + 3], hx_, w3_, acc[(base) + 3]); } while (0)

    // layer 2: out[n][j] = b2[j] + sum_i h[n][i]*W2[i][j], tile 8n x 8j
    {
        ull acc[32];
        const ull* b2u = (const ull*)b2;
#pragma unroll
        for (int jp = 0; jp < 4; jp++) {
            const ull bb = __ldg(b2u + 4 * bc + jp);
#pragma unroll
            for (int n = 0; n < 8; n++) acc[n * 4 + jp] = bb;
        }
        for (int i = 0; i < 64; i++) {
            float4 h0 = *(const float4*)(hb + i * 32 + a * 8);
            float4 h1 = *(const float4*)(hb + i * 32 + a * 8 + 4);
            ull w0_, w1_, w2_, w3_;
            LDSV2(w0_, w1_, w2a + i * 256 + bc * 32);
            LDSV2(w2_, w3_, w2a + i * 256 + bc * 32 + 16);
            OPROW(h0.x, 0);  OPROW(h0.y, 4);  OPROW(h0.z, 8);  OPROW(h0.w, 12);
            OPROW(h1.x, 16); OPROW(h1.y, 20); OPROW(h1.z, 24); OPROW(h1.w, 28);
        }
        __syncwarp();
#pragma unroll
        for (int jp = 0; jp < 4; jp++) {
            float vlo[8], vhi[8];
#pragma unroll
            for (int n = 0; n < 8; n++) {
                float lo, hi; UNPACK2(lo, hi, acc[n * 4 + jp]);
                vlo[n] = fmaxf(lo, 0.f); vhi[n] = fmaxf(hi, 0.f);
            }
            const int j0 = 8 * bc + 2 * jp;
            *(float4*)(hb + j0 * 32 + a * 8)       = make_float4(vlo[0], vlo[1], vlo[2], vlo[3]);
            *(float4*)(hb + j0 * 32 + a * 8 + 4)   = make_float4(vlo[4], vlo[5], vlo[6], vlo[7]);
            *(float4*)(hb + (j0 + 1) * 32 + a * 8)     = make_float4(vhi[0], vhi[1], vhi[2], vhi[3]);
            *(float4*)(hb + (j0 + 1) * 32 + a * 8 + 4) = make_float4(vhi[4], vhi[5], vhi[6], vhi[7]);
        }
        __syncwarp();
    }

    // layer 3 (two 64-col halves) + relu + max over K
    float* of = outfeat + (size_t)c * 128;
    const ull* b3u = (const ull*)b3;
#pragma unroll 1
    for (int h = 0; h < 2; h++) {
        ull acc[32];
#pragma unroll
        for (int jp = 0; jp < 4; jp++) {
            const ull bb = __ldg(b3u + h * 32 + 4 * bc + jp);
#pragma unroll
            for (int n = 0; n < 8; n++) acc[n * 4 + jp] = bb;
        }
        for (int i = 0; i < 64; i++) {
            float4 h0 = *(const float4*)(hb + i * 32 + a * 8);
            float4 h1 = *(const float4*)(hb + i * 32 + a * 8 + 4);
            ull w0_, w1_, w2_, w3_;
            LDSV2(w0_, w1_, w3a + i * 512 + h * 256 + bc * 32);
            LDSV2(w2_, w3_, w3a + i * 512 + h * 256 + bc * 32 + 16);
            OPROW(h0.x, 0);  OPROW(h0.y, 4);  OPROW(h0.z, 8);  OPROW(h0.w, 12);
            OPROW(h1.x, 16); OPROW(h1.y, 20); OPROW(h1.z, 24); OPROW(h1.w, 28);
        }
        float cm[8];
#pragma unroll
        for (int jp = 0; jp < 4; jp++) {
            float mlo = 0.f, mhi = 0.f;
#pragma unroll
            for (int n = 0; n < 8; n++) {
                float lo, hi; UNPACK2(lo, hi, acc[n * 4 + jp]);
                mlo = fmaxf(mlo, lo); mhi = fmaxf(mhi, hi);
            }
            cm[2 * jp] = mlo; cm[2 * jp + 1] = mhi;
        }
#pragma unroll
        for (int jj = 0; jj < 8; jj++) {
            cm[jj] = fmaxf(cm[jj], __shfl_xor_sync(0xffffffffu, cm[jj], 8));
            cm[jj] = fmaxf(cm[jj], __shfl_xor_sync(0xffffffffu, cm[jj], 16));
        }
        if (a == 0) {
            *(float4*)(of + h * 64 + bc * 8)     = make_float4(cm[0], cm[1], cm[2], cm[3]);
            *(float4*)(of + h * 64 + bc * 8 + 4) = make_float4(cm[4], cm[5], cm[6], cm[7]);
        }
    }
#undef OPROW
}

// ---------------------------------------------------------------------------
extern "C" void kernel_launch(void* const* d_in, const int* in_sizes, int n_in,
                              void* d_out, int out_size)
{
    (void)in_sizes; (void)n_in; (void)out_size;
    const float* xyz  = (const float*)d_in[0];
    const float* feat = (const float*)d_in[1];
    const float* W1   = (const float*)d_in[2];
    const float* b1   = (const float*)d_in[3];
    const float* W2   = (const float*)d_in[4];
    const float* b2   = (const float*)d_in[5];
    const float* W3   = (const float*)d_in[6];
    const float* b3   = (const float*)d_in[7];

    float* newxyz  = (float*)d_out;                       // [B,S,3]
    float* outfeat = newxyz + (size_t)BB * SS * 3;        // [B,S,128]

    cudaFuncSetAttribute(fps_kernel, cudaFuncAttributeMaxDynamicSharedMemorySize, 3 * NN * 4);
    cudaFuncSetAttribute(knn_kernel, cudaFuncAttributeMaxDynamicSharedMemorySize, CHUNK * 16);
    cudaFuncSetAttribute(mlp_kernel, cudaFuncAttributeMaxDynamicSharedMemorySize, 114688);

    pregemm_kernel<<<BB * NN / 256, 256>>>(feat, W1);
    fps_kernel<<<BB * FPS_CTAS, 256, 3 * NN * 4>>>(xyz, newxyz);
    knn_kernel<<<BB * SS / 16, 512, CHUNK * 16>>>(xyz, newxyz);
    mlp_kernel<<<BB * SS / 8, 256, 114688>>>(xyz, newxyz, W1, b1, W2, b2, W3, b3, outfeat);
}

// round 14
// speedup vs baseline: 1.0558x; 1.0476x over previous
#include <cuda_runtime.h>
#include <cstdint>
#include <cstddef>

#define BB 8
#define NN 16384
#define CC 64
#define SS 2048
#define KK 32

typedef unsigned long long ull;

// Scratch (device globals: no allocation allowed)
__device__ float g_feat1[(size_t)BB * NN * 64];   // features @ W1[3:67,:]
__device__ int   g_knn[(size_t)BB * SS * KK];     // top-32 neighbor indices

#define ADD2(r,a,b) asm("add.rn.f32x2 %0,%1,%2;" : "=l"(r) : "l"(a), "l"(b))
#define MUL2(r,a,b) asm("mul.rn.f32x2 %0,%1,%2;" : "=l"(r) : "l"(a), "l"(b))
#define FMA2(r,a,b,c) asm("fma.rn.f32x2 %0,%1,%2,%3;" : "=l"(r) : "l"(a), "l"(b), "l"(c))
#define PACK2(r,lo,hi) asm("mov.b64 %0,{%1,%2};" : "=l"(r) : "f"(lo), "f"(hi))
#define UNPACK2(lo,hi,v) asm("mov.b64 {%0,%1},%2;" : "=f"(lo), "=f"(hi) : "l"(v))

__device__ __forceinline__ uint32_t smem_u32(const void* p) {
    uint32_t a;
    asm("{ .reg .u64 t; cvta.to.shared.u64 t, %1; cvt.u32.u64 %0, t; }" : "=r"(a) : "l"(p));
    return a;
}
__device__ __forceinline__ uint32_t cluster_rank() {
    uint32_t r; asm("mov.u32 %0, %%cluster_ctarank;" : "=r"(r)); return r;
}
__device__ __forceinline__ void st_cluster_u64(uint32_t laddr, uint32_t rnk, ull v) {
    asm volatile("{ .reg .b32 ra; mapa.shared::cluster.u32 ra, %0, %1; "
                 "st.shared::cluster.u64 [ra], %2; }"
                 :: "r"(laddr), "r"(rnk), "l"(v) : "memory");
}
#define MBARRIER_INIT(a, cnt) \
    asm volatile("mbarrier.init.shared.b64 [%0], %1;" :: "r"(a), "r"((uint32_t)(cnt)) : "memory")
#define MBARRIER_ARRIVE_CLUSTER(a, rnk) \
    asm volatile("{ .reg .b32 ra; mapa.shared::cluster.u32 ra, %0, %1; " \
                 "mbarrier.arrive.shared::cluster.b64 _, [ra]; }" \
                 :: "r"(a), "r"((uint32_t)(rnk)) : "memory")
#define MBARRIER_WAIT_PARITY(a, par) do {                                   \
    uint32_t _m = (a), _p = (uint32_t)(par), _d;                            \
    asm volatile("{ .reg .pred p; "                                         \
        "mbarrier.try_wait.parity.acquire.cta.shared::cta.b64 p, [%1], %2; " \
        "selp.b32 %0, 1, 0, p; }" : "=r"(_d) : "r"(_m), "r"(_p) : "memory"); \
    if (!_d) {                                                              \
        asm volatile("{ .reg .pred P1; WL_%=: "                             \
            "mbarrier.try_wait.parity.acquire.cta.shared::cta.b64 P1, [%0], %1, 0x989680; " \
            "@P1 bra.uni WD_%=; bra.uni WL_%=; WD_%=: }"                    \
            :: "r"(_m), "r"(_p) : "memory");                                \
    }                                                                       \
} while (0)
#define CLUSTER_SYNC() do { \
    asm volatile("barrier.cluster.arrive.aligned;" ::: "memory"); \
    asm volatile("barrier.cluster.wait.aligned;" ::: "memory"); } while (0)

#define LDSV2(w0, w1, addr) \
    asm("ld.shared.v2.u64 {%0,%1}, [%2];" : "=l"(w0), "=l"(w1) : "r"(addr))

// depth-3 max tree over 8 u64 keys loaded as 4x ulonglong2
__device__ __forceinline__ ull max8_tree(const ull* k8) {
    const ulonglong2* rk = (const ulonglong2*)k8;
    ulonglong2 e0 = rk[0], e1 = rk[1], e2 = rk[2], e3 = rk[3];
    ull m0 = e0.x > e0.y ? e0.x : e0.y;
    ull m1 = e1.x > e1.y ? e1.x : e1.y;
    ull m2 = e2.x > e2.y ? e2.x : e2.y;
    ull m3 = e3.x > e3.y ? e3.x : e3.y;
    m0 = m0 > m1 ? m0 : m1;
    m2 = m2 > m3 ? m2 : m3;
    return m0 > m2 ? m0 : m2;
}

// ---------------------------------------------------------------------------
// Stage 1: FPS, 8-CTA cluster per batch (R12/R13-measured form, ~886us).
// Distance arithmetic bit-identical to R2..R13.
// ---------------------------------------------------------------------------
#define FPS_CTAS 8
#define FPS_PTS (NN / FPS_CTAS)   // 2048 per slice, 8 pts (4 pairs)/thread

__global__ __launch_bounds__(256, 1) __cluster_dims__(FPS_CTAS, 1, 1)
void fps_kernel(const float* __restrict__ xyz, float* __restrict__ newxyz)
{
    extern __shared__ float smf[];          // sx[NN] sy[NN] sz[NN] = 192KB
    float* sx = smf;
    float* sy = smf + NN;
    float* sz = smf + 2 * NN;
    __shared__ alignas(16) ull redk[8];
    __shared__ alignas(16) ull mbox[2][FPS_CTAS];
    __shared__ alignas(8) ull mbar;

    const unsigned rank = cluster_rank();
    const int b = blockIdx.x / FPS_CTAS;
    const int t = threadIdx.x;
    const int w = t >> 5, l = t & 31;
    const float* base = xyz + (size_t)b * NN * 3;
    for (int i = t; i < NN; i += 256) {
        sx[i] = base[3 * i + 0];
        sy[i] = base[3 * i + 1];
        sz[i] = base[3 * i + 2];
    }
    const uint32_t mbar_a = smem_u32(&mbar);
    if (t == 0) MBARRIER_INIT(mbar_a, FPS_CTAS);
    __syncthreads();
    CLUSTER_SYNC();

    const int pbase = rank * FPS_PTS;
    ull px[4], py[4], pz[4];
    float dist[8];
#pragma unroll
    for (int k = 0; k < 4; k++) {
        const int p = pbase + 2 * (t + 256 * k);
        px[k] = *(const ull*)(sx + p);
        py[k] = *(const ull*)(sy + p);
        pz[k] = *(const ull*)(sz + p);
        dist[2 * k] = 1e10f; dist[2 * k + 1] = 1e10f;
    }

    const uint32_t mbox_a = smem_u32(&mbox[0][rank]);
    float cx = sx[0], cy = sy[0], cz = sz[0];
    float* outp = newxyz + (size_t)b * SS * 3;

    for (int s = 0; s < SS; s++) {
        if (rank == 0 && t == 0) {
            outp[3 * s + 0] = cx; outp[3 * s + 1] = cy; outp[3 * s + 2] = cz;
        }
        ull ncx, ncy, ncz;
        {
            float mx0 = -cx, my0 = -cy, mz0 = -cz;
            PACK2(ncx, mx0, mx0); PACK2(ncy, my0, my0); PACK2(ncz, mz0, mz0);
        }
        float bv = -1.0f; int bi = 0;
#pragma unroll
        for (int k = 0; k < 4; k++) {
            ull dx, dy, dz, xx, yy, zz, s1, dd;
            ADD2(dx, px[k], ncx);
            ADD2(dy, py[k], ncy);
            ADD2(dz, pz[k], ncz);
            MUL2(xx, dx, dx);
            MUL2(yy, dy, dy);
            MUL2(zz, dz, dz);
            ADD2(s1, xx, yy);
            ADD2(dd, s1, zz);
            float d0, d1; UNPACK2(d0, d1, dd);
            float a0 = fminf(dist[2 * k], d0);     dist[2 * k] = a0;
            float a1 = fminf(dist[2 * k + 1], d1); dist[2 * k + 1] = a1;
            const int pl = 2 * (t + 256 * k);
            if (a0 > bv) { bv = a0; bi = pl; }
            if (a1 > bv) { bv = a1; bi = pl + 1; }
        }
        const int gbi = pbase + bi;                // global index
        const unsigned vb = __float_as_uint(bv);   // dist >= 0 -> bit-order ok
        const unsigned wv = __reduce_max_sync(0xffffffffu, vb);
        const unsigned cand = (vb == wv) ? (unsigned)~gbi : 0u;
        const unsigned wni = __reduce_max_sync(0xffffffffu, cand); // ~idx max = idx min
        if (l == 0) redk[w] = ((ull)wv << 32) | wni;
        __syncthreads();
        const int par = s & 1;
        if (w == 0) {
            const ull best = max8_tree(redk);      // depth-3 tree fold
            if (l < FPS_CTAS) {
                st_cluster_u64(mbox_a + par * (FPS_CTAS * 8), l, best);
                MBARRIER_ARRIVE_CLUSTER(mbar_a, l);
            }
        }
        MBARRIER_WAIT_PARITY(mbar_a, par);
        const ull bk = max8_tree(mbox[par]);       // depth-3 tree fold
        const unsigned widx = ~(unsigned)bk;
        cx = sx[widx]; cy = sy[widx]; cz = sz[widx];
    }
}

// ---------------------------------------------------------------------------
// Stage 2: 32 nearest neighbors per centroid. NEW: 2 candidates per lane per
// step (64/step) — halves per-step fixed costs (ballot latency, branch,
// address math); the two distance chains are ILP-independent. Selection
// semantics identical to R13: ascending index order, strict < vs tau.
// ---------------------------------------------------------------------------
#define CHUNK 8192

#define KNN_PROCESS(wantv, du, base) \
    while (wantv) { \
        const int leader_ = __ffs(wantv) - 1; \
        wantv &= (wantv - 1); \
        unsigned cb_ = __shfl_sync(0xffffffffu, du, leader_); \
        if (cb_ < tau) { \
            unsigned rm_ = __ballot_sync(0xffffffffu, val == tau); \
            const int r_ = __ffs(rm_) - 1; \
            if (l == r_) { val = cb_; idx = (base) + leader_; } \
            tau = __reduce_max_sync(0xffffffffu, val); \
        } \
    }

__global__ __launch_bounds__(512, 1) void knn_kernel(const float* __restrict__ xyz,
                                                     const float* __restrict__ newxyz)
{
    const int blk = blockIdx.x;
    const int b = blk >> 7;
    const int s0 = (blk & 127) * 16;
    extern __shared__ float4 sp[];
    const int tid = threadIdx.x, w = tid >> 5, l = tid & 31;
    const int srow = s0 + w;
    const float* q = newxyz + ((size_t)b * SS + srow) * 3;
    const float qx = q[0], qy = q[1], qz = q[2];
    const float q2 = __fadd_rn(__fadd_rn(__fmul_rn(qx, qx), __fmul_rn(qy, qy)),
                               __fmul_rn(qz, qz));
    unsigned val = 0, tau = 0;
    int idx = 0;
    const float* base = xyz + (size_t)b * NN * 3;

    for (int c = 0; c < 2; c++) {
        const int nb = c * CHUNK;
        for (int i = tid; i < CHUNK; i += 512) {
            const float x = base[3 * (nb + i) + 0];
            const float y = base[3 * (nb + i) + 1];
            const float z = base[3 * (nb + i) + 2];
            const float x2 = __fadd_rn(__fadd_rn(__fmul_rn(x, x), __fmul_rn(y, y)),
                                       __fmul_rn(z, z));
            sp[i] = make_float4(x, y, z, x2);
        }
        __syncthreads();

        int n0 = 0;
        if (c == 0) {
            // seed: indices 0-31 distributed one per lane
            float4 p = sp[l];
            float cross = __fmaf_rn(p.z, qz, __fmaf_rn(p.y, qy, __fmul_rn(p.x, qx)));
            float d = __fmaf_rn(-2.f, cross, __fadd_rn(q2, p.w));
            unsigned bb = __float_as_uint(d);
            val = bb ^ (unsigned)(((int)bb >> 31) | 0x80000000);
            idx = l;
            tau = __reduce_max_sync(0xffffffffu, val);
            // single half-step for indices 32-63 to re-align to 64
            float4 p1 = sp[32 + l];
            float cr1 = __fmaf_rn(p1.z, qz, __fmaf_rn(p1.y, qy, __fmul_rn(p1.x, qx)));
            float d1 = __fmaf_rn(-2.f, cr1, __fadd_rn(q2, p1.w));
            unsigned b1 = __float_as_uint(d1);
            unsigned du1 = b1 ^ (unsigned)(((int)b1 >> 31) | 0x80000000);
            unsigned want1 = __ballot_sync(0xffffffffu, du1 < tau);
            KNN_PROCESS(want1, du1, 32);
            n0 = 64;
        }
        for (; n0 < CHUNK; n0 += 64) {
            float4 p0 = sp[n0 + l];
            float4 p1 = sp[n0 + 32 + l];
            float cr0 = __fmaf_rn(p0.z, qz, __fmaf_rn(p0.y, qy, __fmul_rn(p0.x, qx)));
            float cr1 = __fmaf_rn(p1.z, qz, __fmaf_rn(p1.y, qy, __fmul_rn(p1.x, qx)));
            float d0 = __fmaf_rn(-2.f, cr0, __fadd_rn(q2, p0.w));
            float d1 = __fmaf_rn(-2.f, cr1, __fadd_rn(q2, p1.w));
            unsigned b0 = __float_as_uint(d0);
            unsigned b1 = __float_as_uint(d1);
            unsigned du0 = b0 ^ (unsigned)(((int)b0 >> 31) | 0x80000000);
            unsigned du1 = b1 ^ (unsigned)(((int)b1 >> 31) | 0x80000000);
            unsigned want0 = __ballot_sync(0xffffffffu, du0 < tau);
            KNN_PROCESS(want0, du0, nb + n0);
            unsigned want1 = __ballot_sync(0xffffffffu, du1 < tau);
            KNN_PROCESS(want1, du1, nb + n0 + 32);
        }
        __syncthreads();
    }
    g_knn[((size_t)b * SS + srow) * KK + l] = idx;
}

// ---------------------------------------------------------------------------
// Stage 3: per-point pre-transform feat1 = features @ W1[3:67,:] (unchanged)
// ---------------------------------------------------------------------------
__global__ __launch_bounds__(256, 1) void pregemm_kernel(const float* __restrict__ feat,
                                                         const float* __restrict__ W1)
{
    __shared__ float sw[64 * 64];
    for (int i = threadIdx.x; i < 64 * 64; i += 256) sw[i] = W1[192 + i];
    __syncthreads();
    const int row = blockIdx.x * 256 + threadIdx.x;
    const float4* f4 = (const float4*)(feat + (size_t)row * 64);
    float acc[64];
#pragma unroll
    for (int j = 0; j < 64; j++) acc[j] = 0.f;
    for (int i4 = 0; i4 < 16; i4++) {
        float4 fv = f4[i4];
        const float4* w0 = (const float4*)(sw + (i4 * 4 + 0) * 64);
        const float4* w1 = (const float4*)(sw + (i4 * 4 + 1) * 64);
        const float4* w2 = (const float4*)(sw + (i4 * 4 + 2) * 64);
        const float4* w3 = (const float4*)(sw + (i4 * 4 + 3) * 64);
#pragma unroll
        for (int jv = 0; jv < 16; jv++) {
            float4 a0 = w0[jv], a1 = w1[jv], a2 = w2[jv], a3 = w3[jv];
            acc[jv * 4 + 0] = fmaf(fv.x, a0.x, fmaf(fv.y, a1.x, fmaf(fv.z, a2.x, fmaf(fv.w, a3.x, acc[jv * 4 + 0]))));
            acc[jv * 4 + 1] = fmaf(fv.x, a0.y, fmaf(fv.y, a1.y, fmaf(fv.z, a2.y, fmaf(fv.w, a3.y, acc[jv * 4 + 1]))));
            acc[jv * 4 + 2] = fmaf(fv.x, a0.z, fmaf(fv.y, a1.z, fmaf(fv.z, a2.z, fmaf(fv.w, a3.z, acc[jv * 4 + 2]))));
            acc[jv * 4 + 3] = fmaf(fv.x, a0.w, fmaf(fv.y, a1.w, fmaf(fv.z, a2.w, fmaf(fv.w, a3.w, acc[jv * 4 + 3]))));
        }
    }
    float4* o4 = (float4*)(g_feat1 + (size_t)row * 64);
#pragma unroll
    for (int jv = 0; jv < 16; jv++)
        o4[jv] = make_float4(acc[jv * 4], acc[jv * 4 + 1], acc[jv * 4 + 2], acc[jv * 4 + 3]);
}

// ---------------------------------------------------------------------------
// Stage 4: gather + MLP + max over K (R10/R13-measured form, 358us).
// ---------------------------------------------------------------------------
__global__ __launch_bounds__(256, 2) void mlp_kernel(const float* __restrict__ xyz,
                                                     const float* __restrict__ newxyz,
                                                     const float* __restrict__ W1,
                                                     const float* __restrict__ b1,
                                                     const float* __restrict__ W2,
                                                     const float* __restrict__ b2,
                                                     const float* __restrict__ W3,
                                                     const float* __restrict__ b3,
                                                     float* __restrict__ outfeat)
{
    extern __shared__ float smf2[];
    float* sW2 = smf2;             // 64*64
    float* sW3 = smf2 + 4096;      // 64*128
    float* hbuf = smf2 + 12288;    // 8 warps * 2048

    const int tid = threadIdx.x;
    for (int i = tid; i < 4096; i += 256) sW2[i] = W2[i];
    for (int i = tid; i < 8192; i += 256) sW3[i] = W3[i];
    __syncthreads();

    const int w = tid >> 5, l = tid & 31;
    const int a = l >> 3;          // neighbor group (0..3)
    const int bc = l & 7;          // column group (0..7)
    const int c = blockIdx.x * 8 + w;
    const int b = c / SS;
    float* hb = hbuf + w * 2048;
    const uint32_t w2a = smem_u32(sW2);
    const uint32_t w3a = smem_u32(sW3);

    const int nb = g_knn[(size_t)c * KK + l];
    const float* p = xyz + ((size_t)b * NN + nb) * 3;
    const float px = p[0], py = p[1], pz = p[2];
    const float* q = newxyz + (size_t)c * 3;
    const float dx = px - q[0], dy = py - q[1], dz = pz - q[2];
    const float4* fg = (const float4*)(g_feat1 + ((size_t)b * NN + nb) * 64);

    // layer 1: feat1(gathered) + xyz_norm @ W1[0:3] + b1, relu -> hb[ch*32+l]
#pragma unroll
    for (int jv = 0; jv < 16; jv++) {
        float4 f = fg[jv];
        float4 bb = __ldg((const float4*)b1 + jv);
        float4 u0 = __ldg((const float4*)(W1) + jv);
        float4 u1 = __ldg((const float4*)(W1 + 64) + jv);
        float4 u2 = __ldg((const float4*)(W1 + 128) + jv);
        hb[(jv * 4 + 0) * 32 + l] = fmaxf(fmaf(dz, u2.x, fmaf(dy, u1.x, fmaf(dx, u0.x, f.x + bb.x))), 0.f);
        hb[(jv * 4 + 1) * 32 + l] = fmaxf(fmaf(dz, u2.y, fmaf(dy, u1.y, fmaf(dx, u0.y, f.y + bb.y))), 0.f);
        hb[(jv * 4 + 2) * 32 + l] = fmaxf(fmaf(dz, u2.z, fmaf(dy, u1.z, fmaf(dx, u0.z, f.z + bb.z))), 0.f);
        hb[(jv * 4 + 3) * 32 + l] = fmaxf(fmaf(dz, u2.w, fmaf(dy, u1.w, fmaf(dx, u0.w, f.w + bb.w))), 0.f);
    }
    __syncwarp();

#define OPROW(hval, base) do { ull hx_; PACK2(hx_, hval, hval);            \
        FMA2(acc[(base) + 0], hx_, w0_, acc[(base) + 0]);                   \
        FMA2(acc[(base) + 1], hx_, w1_, acc[(base) + 1]);                   \
        FMA2(acc[(base) + 2], hx_, w2_, acc[(base) + 2]);                   \
        FMA2(acc[(base) + 3], hx_, w3_, acc[(base) + 3]); } while (0)

    // layer 2: out[n][j] = b2[j] + sum_i h[n][i]*W2[i][j], tile 8n x 8j
    {
        ull acc[32];
        const ull* b2u = (const ull*)b2;
#pragma unroll
        for (int jp = 0; jp < 4; jp++) {
            const ull bb = __ldg(b2u + 4 * bc + jp);
#pragma unroll
            for (int n = 0; n < 8; n++) acc[n * 4 + jp] = bb;
        }
        for (int i = 0; i < 64; i++) {
            float4 h0 = *(const float4*)(hb + i * 32 + a * 8);
            float4 h1 = *(const float4*)(hb + i * 32 + a * 8 + 4);
            ull w0_, w1_, w2_, w3_;
            LDSV2(w0_, w1_, w2a + i * 256 + bc * 32);
            LDSV2(w2_, w3_, w2a + i * 256 + bc * 32 + 16);
            OPROW(h0.x, 0);  OPROW(h0.y, 4);  OPROW(h0.z, 8);  OPROW(h0.w, 12);
            OPROW(h1.x, 16); OPROW(h1.y, 20); OPROW(h1.z, 24); OPROW(h1.w, 28);
        }
        __syncwarp();
#pragma unroll
        for (int jp = 0; jp < 4; jp++) {
            float vlo[8], vhi[8];
#pragma unroll
            for (int n = 0; n < 8; n++) {
                float lo, hi; UNPACK2(lo, hi, acc[n * 4 + jp]);
                vlo[n] = fmaxf(lo, 0.f); vhi[n] = fmaxf(hi, 0.f);
            }
            const int j0 = 8 * bc + 2 * jp;
            *(float4*)(hb + j0 * 32 + a * 8)       = make_float4(vlo[0], vlo[1], vlo[2], vlo[3]);
            *(float4*)(hb + j0 * 32 + a * 8 + 4)   = make_float4(vlo[4], vlo[5], vlo[6], vlo[7]);
            *(float4*)(hb + (j0 + 1) * 32 + a * 8)     = make_float4(vhi[0], vhi[1], vhi[2], vhi[3]);
            *(float4*)(hb + (j0 + 1) * 32 + a * 8 + 4) = make_float4(vhi[4], vhi[5], vhi[6], vhi[7]);
        }
        __syncwarp();
    }

    // layer 3 (two 64-col halves) + relu + max over K
    float* of = outfeat + (size_t)c * 128;
    const ull* b3u = (const ull*)b3;
#pragma unroll 1
    for (int h = 0; h < 2; h++) {
        ull acc[32];
#pragma unroll
        for (int jp = 0; jp < 4; jp++) {
            const ull bb = __ldg(b3u + h * 32 + 4 * bc + jp);
#pragma unroll
            for (int n = 0; n < 8; n++) acc[n * 4 + jp] = bb;
        }
        for (int i = 0; i < 64; i++) {
            float4 h0 = *(const float4*)(hb + i * 32 + a * 8);
            float4 h1 = *(const float4*)(hb + i * 32 + a * 8 + 4);
            ull w0_, w1_, w2_, w3_;
            LDSV2(w0_, w1_, w3a + i * 512 + h * 256 + bc * 32);
            LDSV2(w2_, w3_, w3a + i * 512 + h * 256 + bc * 32 + 16);
            OPROW(h0.x, 0);  OPROW(h0.y, 4);  OPROW(h0.z, 8);  OPROW(h0.w, 12);
            OPROW(h1.x, 16); OPROW(h1.y, 20); OPROW(h1.z, 24); OPROW(h1.w, 28);
        }
        float cm[8];
#pragma unroll
        for (int jp = 0; jp < 4; jp++) {
            float mlo = 0.f, mhi = 0.f;
#pragma unroll
            for (int n = 0; n < 8; n++) {
                float lo, hi; UNPACK2(lo, hi, acc[n * 4 + jp]);
                mlo = fmaxf(mlo, lo); mhi = fmaxf(mhi, hi);
            }
            cm[2 * jp] = mlo; cm[2 * jp + 1] = mhi;
        }
#pragma unroll
        for (int jj = 0; jj < 8; jj++) {
            cm[jj] = fmaxf(cm[jj], __shfl_xor_sync(0xffffffffu, cm[jj], 8));
            cm[jj] = fmaxf(cm[jj], __shfl_xor_sync(0xffffffffu, cm[jj], 16));
        }
        if (a == 0) {
            *(float4*)(of + h * 64 + bc * 8)     = make_float4(cm[0], cm[1], cm[2], cm[3]);
            *(float4*)(of + h * 64 + bc * 8 + 4) = make_float4(cm[4], cm[5], cm[6], cm[7]);
        }
    }
#undef OPROW
}

// ---------------------------------------------------------------------------
extern "C" void kernel_launch(void* const* d_in, const int* in_sizes, int n_in,
                              void* d_out, int out_size)
{
    (void)in_sizes; (void)n_in; (void)out_size;
    const float* xyz  = (const float*)d_in[0];
    const float* feat = (const float*)d_in[1];
    const float* W1   = (const float*)d_in[2];
    const float* b1   = (const float*)d_in[3];
    const float* W2   = (const float*)d_in[4];
    const float* b2   = (const float*)d_in[5];
    const float* W3   = (const float*)d_in[6];
    const float* b3   = (const float*)d_in[7];

    float* newxyz  = (float*)d_out;                       // [B,S,3]
    float* outfeat = newxyz + (size_t)BB * SS * 3;        // [B,S,128]

    cudaFuncSetAttribute(fps_kernel, cudaFuncAttributeMaxDynamicSharedMemorySize, 3 * NN * 4);
    cudaFuncSetAttribute(knn_kernel, cudaFuncAttributeMaxDynamicSharedMemorySize, CHUNK * 16);
    cudaFuncSetAttribute(mlp_kernel, cudaFuncAttributeMaxDynamicSharedMemorySize, 114688);

    pregemm_kernel<<<BB * NN / 256, 256>>>(feat, W1);
    fps_kernel<<<BB * FPS_CTAS, 256, 3 * NN * 4>>>(xyz, newxyz);
    knn_kernel<<<BB * SS / 16, 512, CHUNK * 16>>>(xyz, newxyz);
    mlp_kernel<<<BB * SS / 8, 256, 114688>>>(xyz, newxyz, W1, b1, W2, b2, W3, b3, outfeat);
}

// round 16
// speedup vs baseline: 1.0672x; 1.0108x over previous
#include <cuda_runtime.h>
#include <cstdint>
#include <cstddef>

#define BB 8
#define NN 16384
#define CC 64
#define SS 2048
#define KK 32

typedef unsigned long long ull;

// Scratch (device globals: no allocation allowed)
__device__ float g_feat1[(size_t)BB * NN * 64];   // features @ W1[3:67,:]
__device__ int   g_knn[(size_t)BB * SS * KK];     // top-32 neighbor indices

#define ADD2(r,a,b) asm("add.rn.f32x2 %0,%1,%2;" : "=l"(r) : "l"(a), "l"(b))
#define MUL2(r,a,b) asm("mul.rn.f32x2 %0,%1,%2;" : "=l"(r) : "l"(a), "l"(b))
#define FMA2(r,a,b,c) asm("fma.rn.f32x2 %0,%1,%2,%3;" : "=l"(r) : "l"(a), "l"(b), "l"(c))
#define PACK2(r,lo,hi) asm("mov.b64 %0,{%1,%2};" : "=l"(r) : "f"(lo), "f"(hi))
#define UNPACK2(lo,hi,v) asm("mov.b64 {%0,%1},%2;" : "=f"(lo), "=f"(hi) : "l"(v))

__device__ __forceinline__ uint32_t smem_u32(const void* p) {
    uint32_t a;
    asm("{ .reg .u64 t; cvta.to.shared.u64 t, %1; cvt.u32.u64 %0, t; }" : "=r"(a) : "l"(p));
    return a;
}
__device__ __forceinline__ uint32_t cluster_rank() {
    uint32_t r; asm("mov.u32 %0, %%cluster_ctarank;" : "=r"(r)); return r;
}
__device__ __forceinline__ void st_cluster_u64(uint32_t laddr, uint32_t rnk, ull v) {
    asm volatile("{ .reg .b32 ra; mapa.shared::cluster.u32 ra, %0, %1; "
                 "st.shared::cluster.u64 [ra], %2; }"
                 :: "r"(laddr), "r"(rnk), "l"(v) : "memory");
}
#define MBARRIER_INIT(a, cnt) \
    asm volatile("mbarrier.init.shared.b64 [%0], %1;" :: "r"(a), "r"((uint32_t)(cnt)) : "memory")
#define MBARRIER_ARRIVE_CLUSTER(a, rnk) \
    asm volatile("{ .reg .b32 ra; mapa.shared::cluster.u32 ra, %0, %1; " \
                 "mbarrier.arrive.shared::cluster.b64 _, [ra]; }" \
                 :: "r"(a), "r"((uint32_t)(rnk)) : "memory")
#define MBARRIER_WAIT_PARITY(a, par) do {                                   \
    uint32_t _m = (a), _p = (uint32_t)(par), _d;                            \
    asm volatile("{ .reg .pred p; "                                         \
        "mbarrier.try_wait.parity.acquire.cta.shared::cta.b64 p, [%1], %2; " \
        "selp.b32 %0, 1, 0, p; }" : "=r"(_d) : "r"(_m), "r"(_p) : "memory"); \
    if (!_d) {                                                              \
        asm volatile("{ .reg .pred P1; WL_%=: "                             \
            "mbarrier.try_wait.parity.acquire.cta.shared::cta.b64 P1, [%0], %1, 0x989680; " \
            "@P1 bra.uni WD_%=; bra.uni WL_%=; WD_%=: }"                    \
            :: "r"(_m), "r"(_p) : "memory");                                \
    }                                                                       \
} while (0)
#define CLUSTER_SYNC() do { \
    asm volatile("barrier.cluster.arrive.aligned;" ::: "memory"); \
    asm volatile("barrier.cluster.wait.aligned;" ::: "memory"); } while (0)

#define LDSV2(w0, w1, addr) \
    asm("ld.shared.v2.u64 {%0,%1}, [%2];" : "=l"(w0), "=l"(w1) : "r"(addr))

// depth-3 max tree over 8 u64 keys loaded as 4x ulonglong2
__device__ __forceinline__ ull max8_tree(const ull* k8) {
    const ulonglong2* rk = (const ulonglong2*)k8;
    ulonglong2 e0 = rk[0], e1 = rk[1], e2 = rk[2], e3 = rk[3];
    ull m0 = e0.x > e0.y ? e0.x : e0.y;
    ull m1 = e1.x > e1.y ? e1.x : e1.y;
    ull m2 = e2.x > e2.y ? e2.x : e2.y;
    ull m3 = e3.x > e3.y ? e3.x : e3.y;
    m0 = m0 > m1 ? m0 : m1;
    m2 = m2 > m3 ? m2 : m3;
    return m0 > m2 ? m0 : m2;
}

// ---------------------------------------------------------------------------
// Stage 1: FPS, 8-CTA cluster per batch — EXACT R12/R13/R14-measured form
// (885.9us, proven across 3 passing runs). 256 threads, select-chain argmax,
// REDUX pair, one BAR, warp0 tree-folds 8 keys + pushes CTA-best to all
// ranks, cta-scope acquire wait, tree-fold mailbox, local coord lookup.
// ---------------------------------------------------------------------------
#define FPS_CTAS 8
#define FPS_PTS (NN / FPS_CTAS)   // 2048 per slice, 8 pts (4 pairs)/thread

__global__ __launch_bounds__(256, 1) __cluster_dims__(FPS_CTAS, 1, 1)
void fps_kernel(const float* __restrict__ xyz, float* __restrict__ newxyz)
{
    extern __shared__ float smf[];          // sx[NN] sy[NN] sz[NN] = 192KB
    float* sx = smf;
    float* sy = smf + NN;
    float* sz = smf + 2 * NN;
    __shared__ alignas(16) ull redk[8];
    __shared__ alignas(16) ull mbox[2][FPS_CTAS];
    __shared__ alignas(8) ull mbar;

    const unsigned rank = cluster_rank();
    const int b = blockIdx.x / FPS_CTAS;
    const int t = threadIdx.x;
    const int w = t >> 5, l = t & 31;
    const float* base = xyz + (size_t)b * NN * 3;
    for (int i = t; i < NN; i += 256) {
        sx[i] = base[3 * i + 0];
        sy[i] = base[3 * i + 1];
        sz[i] = base[3 * i + 2];
    }
    const uint32_t mbar_a = smem_u32(&mbar);
    if (t == 0) MBARRIER_INIT(mbar_a, FPS_CTAS);
    __syncthreads();
    CLUSTER_SYNC();

    const int pbase = rank * FPS_PTS;
    ull px[4], py[4], pz[4];
    float dist[8];
#pragma unroll
    for (int k = 0; k < 4; k++) {
        const int p = pbase + 2 * (t + 256 * k);
        px[k] = *(const ull*)(sx + p);
        py[k] = *(const ull*)(sy + p);
        pz[k] = *(const ull*)(sz + p);
        dist[2 * k] = 1e10f; dist[2 * k + 1] = 1e10f;
    }

    const uint32_t mbox_a = smem_u32(&mbox[0][rank]);
    float cx = sx[0], cy = sy[0], cz = sz[0];
    float* outp = newxyz + (size_t)b * SS * 3;

    for (int s = 0; s < SS; s++) {
        if (rank == 0 && t == 0) {
            outp[3 * s + 0] = cx; outp[3 * s + 1] = cy; outp[3 * s + 2] = cz;
        }
        ull ncx, ncy, ncz;
        {
            float mx0 = -cx, my0 = -cy, mz0 = -cz;
            PACK2(ncx, mx0, mx0); PACK2(ncy, my0, my0); PACK2(ncz, mz0, mz0);
        }
        float bv = -1.0f; int bi = 0;
#pragma unroll
        for (int k = 0; k < 4; k++) {
            ull dx, dy, dz, xx, yy, zz, s1, dd;
            ADD2(dx, px[k], ncx);
            ADD2(dy, py[k], ncy);
            ADD2(dz, pz[k], ncz);
            MUL2(xx, dx, dx);
            MUL2(yy, dy, dy);
            MUL2(zz, dz, dz);
            ADD2(s1, xx, yy);
            ADD2(dd, s1, zz);
            float d0, d1; UNPACK2(d0, d1, dd);
            float a0 = fminf(dist[2 * k], d0);     dist[2 * k] = a0;
            float a1 = fminf(dist[2 * k + 1], d1); dist[2 * k + 1] = a1;
            const int pl = 2 * (t + 256 * k);
            if (a0 > bv) { bv = a0; bi = pl; }
            if (a1 > bv) { bv = a1; bi = pl + 1; }
        }
        const int gbi = pbase + bi;                // global index
        const unsigned vb = __float_as_uint(bv);   // dist >= 0 -> bit-order ok
        const unsigned wv = __reduce_max_sync(0xffffffffu, vb);
        const unsigned cand = (vb == wv) ? (unsigned)~gbi : 0u;
        const unsigned wni = __reduce_max_sync(0xffffffffu, cand); // ~idx max = idx min
        if (l == 0) redk[w] = ((ull)wv << 32) | wni;
        __syncthreads();
        const int par = s & 1;
        if (w == 0) {
            const ull best = max8_tree(redk);      // depth-3 tree fold
            if (l < FPS_CTAS) {
                st_cluster_u64(mbox_a + par * (FPS_CTAS * 8), l, best);
                MBARRIER_ARRIVE_CLUSTER(mbar_a, l);
            }
        }
        MBARRIER_WAIT_PARITY(mbar_a, par);
        const ull bk = max8_tree(mbox[par]);       // depth-3 tree fold
        const unsigned widx = ~(unsigned)bk;
        cx = sx[widx]; cy = sy[widx]; cz = sz[widx];
    }
}

// ---------------------------------------------------------------------------
// Stage 2: 32 nearest neighbors per centroid. 4 candidates per lane per step
// (128/step) — halves per-step fixed costs vs R14's measured 358us. Strict
// ascending-block order preserves the selected index set exactly.
// ---------------------------------------------------------------------------
#define CHUNK 8192

#define KNN_PROCESS(wantv, du, base) \
    while (wantv) { \
        const int leader_ = __ffs(wantv) - 1; \
        wantv &= (wantv - 1); \
        unsigned cb_ = __shfl_sync(0xffffffffu, du, leader_); \
        if (cb_ < tau) { \
            unsigned rm_ = __ballot_sync(0xffffffffu, val == tau); \
            const int r_ = __ffs(rm_) - 1; \
            if (l == r_) { val = cb_; idx = (base) + leader_; } \
            tau = __reduce_max_sync(0xffffffffu, val); \
        } \
    }

#define KNN_DIST(du, p) \
    { float cr_ = __fmaf_rn((p).z, qz, __fmaf_rn((p).y, qy, __fmul_rn((p).x, qx))); \
      float d_ = __fmaf_rn(-2.f, cr_, __fadd_rn(q2, (p).w)); \
      unsigned b_ = __float_as_uint(d_); \
      du = b_ ^ (unsigned)(((int)b_ >> 31) | 0x80000000); }

__global__ __launch_bounds__(512, 1) void knn_kernel(const float* __restrict__ xyz,
                                                     const float* __restrict__ newxyz)
{
    const int blk = blockIdx.x;
    const int b = blk >> 7;
    const int s0 = (blk & 127) * 16;
    extern __shared__ float4 sp[];
    const int tid = threadIdx.x, w = tid >> 5, l = tid & 31;
    const int srow = s0 + w;
    const float* q = newxyz + ((size_t)b * SS + srow) * 3;
    const float qx = q[0], qy = q[1], qz = q[2];
    const float q2 = __fadd_rn(__fadd_rn(__fmul_rn(qx, qx), __fmul_rn(qy, qy)),
                               __fmul_rn(qz, qz));
    unsigned val = 0, tau = 0;
    int idx = 0;
    const float* base = xyz + (size_t)b * NN * 3;

    for (int c = 0; c < 2; c++) {
        const int nb = c * CHUNK;
        for (int i = tid; i < CHUNK; i += 512) {
            const float x = base[3 * (nb + i) + 0];
            const float y = base[3 * (nb + i) + 1];
            const float z = base[3 * (nb + i) + 2];
            const float x2 = __fadd_rn(__fadd_rn(__fmul_rn(x, x), __fmul_rn(y, y)),
                                       __fmul_rn(z, z));
            sp[i] = make_float4(x, y, z, x2);
        }
        __syncthreads();

        int n0 = 0;
        if (c == 0) {
            // seed: indices 0-31 distributed one per lane
            float4 p = sp[l];
            float cross = __fmaf_rn(p.z, qz, __fmaf_rn(p.y, qy, __fmul_rn(p.x, qx)));
            float d = __fmaf_rn(-2.f, cross, __fadd_rn(q2, p.w));
            unsigned bb = __float_as_uint(d);
            val = bb ^ (unsigned)(((int)bb >> 31) | 0x80000000);
            idx = l;
            tau = __reduce_max_sync(0xffffffffu, val);
            // three half-steps (32..127) to re-align to 128
#pragma unroll
            for (int hs = 32; hs < 128; hs += 32) {
                float4 ph = sp[hs + l];
                unsigned duh; KNN_DIST(duh, ph);
                unsigned wanth = __ballot_sync(0xffffffffu, duh < tau);
                KNN_PROCESS(wanth, duh, hs);
            }
            n0 = 128;
        }
        for (; n0 < CHUNK; n0 += 128) {
            float4 p0 = sp[n0 + l];
            float4 p1 = sp[n0 + 32 + l];
            float4 p2 = sp[n0 + 64 + l];
            float4 p3 = sp[n0 + 96 + l];
            unsigned du0, du1, du2, du3;
            KNN_DIST(du0, p0);
            KNN_DIST(du1, p1);
            KNN_DIST(du2, p2);
            KNN_DIST(du3, p3);
            unsigned want0 = __ballot_sync(0xffffffffu, du0 < tau);
            KNN_PROCESS(want0, du0, nb + n0);
            unsigned want1 = __ballot_sync(0xffffffffu, du1 < tau);
            KNN_PROCESS(want1, du1, nb + n0 + 32);
            unsigned want2 = __ballot_sync(0xffffffffu, du2 < tau);
            KNN_PROCESS(want2, du2, nb + n0 + 64);
            unsigned want3 = __ballot_sync(0xffffffffu, du3 < tau);
            KNN_PROCESS(want3, du3, nb + n0 + 96);
        }
        __syncthreads();
    }
    g_knn[((size_t)b * SS + srow) * KK + l] = idx;
}

// ---------------------------------------------------------------------------
// Stage 3: per-point pre-transform feat1 = features @ W1[3:67,:] (unchanged)
// ---------------------------------------------------------------------------
__global__ __launch_bounds__(256, 1) void pregemm_kernel(const float* __restrict__ feat,
                                                         const float* __restrict__ W1)
{
    __shared__ float sw[64 * 64];
    for (int i = threadIdx.x; i < 64 * 64; i += 256) sw[i] = W1[192 + i];
    __syncthreads();
    const int row = blockIdx.x * 256 + threadIdx.x;
    const float4* f4 = (const float4*)(feat + (size_t)row * 64);
    float acc[64];
#pragma unroll
    for (int j = 0; j < 64; j++) acc[j] = 0.f;
    for (int i4 = 0; i4 < 16; i4++) {
        float4 fv = f4[i4];
        const float4* w0 = (const float4*)(sw + (i4 * 4 + 0) * 64);
        const float4* w1 = (const float4*)(sw + (i4 * 4 + 1) * 64);
        const float4* w2 = (const float4*)(sw + (i4 * 4 + 2) * 64);
        const float4* w3 = (const float4*)(sw + (i4 * 4 + 3) * 64);
#pragma unroll
        for (int jv = 0; jv < 16; jv++) {
            float4 a0 = w0[jv], a1 = w1[jv], a2 = w2[jv], a3 = w3[jv];
            acc[jv * 4 + 0] = fmaf(fv.x, a0.x, fmaf(fv.y, a1.x, fmaf(fv.z, a2.x, fmaf(fv.w, a3.x, acc[jv * 4 + 0]))));
            acc[jv * 4 + 1] = fmaf(fv.x, a0.y, fmaf(fv.y, a1.y, fmaf(fv.z, a2.y, fmaf(fv.w, a3.y, acc[jv * 4 + 1]))));
            acc[jv * 4 + 2] = fmaf(fv.x, a0.z, fmaf(fv.y, a1.z, fmaf(fv.z, a2.z, fmaf(fv.w, a3.z, acc[jv * 4 + 2]))));
            acc[jv * 4 + 3] = fmaf(fv.x, a0.w, fmaf(fv.y, a1.w, fmaf(fv.z, a2.w, fmaf(fv.w, a3.w, acc[jv * 4 + 3]))));
        }
    }
    float4* o4 = (float4*)(g_feat1 + (size_t)row * 64);
#pragma unroll
    for (int jv = 0; jv < 16; jv++)
        o4[jv] = make_float4(acc[jv * 4], acc[jv * 4 + 1], acc[jv * 4 + 2], acc[jv * 4 + 3]);
}

// ---------------------------------------------------------------------------
// Stage 4: gather + MLP + max over K (R10/R13/R14-measured form, ~349us).
// ---------------------------------------------------------------------------
__global__ __launch_bounds__(256, 2) void mlp_kernel(const float* __restrict__ xyz,
                                                     const float* __restrict__ newxyz,
                                                     const float* __restrict__ W1,
                                                     const float* __restrict__ b1,
                                                     const float* __restrict__ W2,
                                                     const float* __restrict__ b2,
                                                     const float* __restrict__ W3,
                                                     const float* __restrict__ b3,
                                                     float* __restrict__ outfeat)
{
    extern __shared__ float smf2[];
    float* sW2 = smf2;             // 64*64
    float* sW3 = smf2 + 4096;      // 64*128
    float* hbuf = smf2 + 12288;    // 8 warps * 2048

    const int tid = threadIdx.x;
    for (int i = tid; i < 4096; i += 256) sW2[i] = W2[i];
    for (int i = tid; i < 8192; i += 256) sW3[i] = W3[i];
    __syncthreads();

    const int w = tid >> 5, l = tid & 31;
    const int a = l >> 3;          // neighbor group (0..3)
    const int bc = l & 7;          // column group (0..7)
    const int c = blockIdx.x * 8 + w;
    const int b = c / SS;
    float* hb = hbuf + w * 2048;
    const uint32_t w2a = smem_u32(sW2);
    const uint32_t w3a = smem_u32(sW3);

    const int nb = g_knn[(size_t)c * KK + l];
    const float* p = xyz + ((size_t)b * NN + nb) * 3;
    const float px = p[0], py = p[1], pz = p[2];
    const float* q = newxyz + (size_t)c * 3;
    const float dx = px - q[0], dy = py - q[1], dz = pz - q[2];
    const float4* fg = (const float4*)(g_feat1 + ((size_t)b * NN + nb) * 64);

    // layer 1: feat1(gathered) + xyz_norm @ W1[0:3] + b1, relu -> hb[ch*32+l]
#pragma unroll
    for (int jv = 0; jv < 16; jv++) {
        float4 f = fg[jv];
        float4 bb = __ldg((const float4*)b1 + jv);
        float4 u0 = __ldg((const float4*)(W1) + jv);
        float4 u1 = __ldg((const float4*)(W1 + 64) + jv);
        float4 u2 = __ldg((const float4*)(W1 + 128) + jv);
        hb[(jv * 4 + 0) * 32 + l] = fmaxf(fmaf(dz, u2.x, fmaf(dy, u1.x, fmaf(dx, u0.x, f.x + bb.x))), 0.f);
        hb[(jv * 4 + 1) * 32 + l] = fmaxf(fmaf(dz, u2.y, fmaf(dy, u1.y, fmaf(dx, u0.y, f.y + bb.y))), 0.f);
        hb[(jv * 4 + 2) * 32 + l] = fmaxf(fmaf(dz, u2.z, fmaf(dy, u1.z, fmaf(dx, u0.z, f.z + bb.z))), 0.f);
        hb[(jv * 4 + 3) * 32 + l] = fmaxf(fmaf(dz, u2.w, fmaf(dy, u1.w, fmaf(dx, u0.w, f.w + bb.w))), 0.f);
    }
    __syncwarp();

#define OPROW(hval, base) do { ull hx_; PACK2(hx_, hval, hval);            \
        FMA2(acc[(base) + 0], hx_, w0_, acc[(base) + 0]);                   \
        FMA2(acc[(base) + 1], hx_, w1_, acc[(base) + 1]);                   \
        FMA2(acc[(base) + 2], hx_, w2_, acc[(base) + 2]);                   \
        FMA2(acc[(base) + 3], hx_, w3_, acc[(base) + 3]); } while (0)

    // layer 2: out[n][j] = b2[j] + sum_i h[n][i]*W2[i][j], tile 8n x 8j
    {
        ull acc[32];
        const ull* b2u = (const ull*)b2;
#pragma unroll
        for (int jp = 0; jp < 4; jp++) {
            const ull bb = __ldg(b2u + 4 * bc + jp);
#pragma unroll
            for (int n = 0; n < 8; n++) acc[n * 4 + jp] = bb;
        }
        for (int i = 0; i < 64; i++) {
            float4 h0 = *(const float4*)(hb + i * 32 + a * 8);
            float4 h1 = *(const float4*)(hb + i * 32 + a * 8 + 4);
            ull w0_, w1_, w2_, w3_;
            LDSV2(w0_, w1_, w2a + i * 256 + bc * 32);
            LDSV2(w2_, w3_, w2a + i * 256 + bc * 32 + 16);
            OPROW(h0.x, 0);  OPROW(h0.y, 4);  OPROW(h0.z, 8);  OPROW(h0.w, 12);
            OPROW(h1.x, 16); OPROW(h1.y, 20); OPROW(h1.z, 24); OPROW(h1.w, 28);
        }
        __syncwarp();
#pragma unroll
        for (int jp = 0; jp < 4; jp++) {
            float vlo[8], vhi[8];
#pragma unroll
            for (int n = 0; n < 8; n++) {
                float lo, hi; UNPACK2(lo, hi, acc[n * 4 + jp]);
                vlo[n] = fmaxf(lo, 0.f); vhi[n] = fmaxf(hi, 0.f);
            }
            const int j0 = 8 * bc + 2 * jp;
            *(float4*)(hb + j0 * 32 + a * 8)       = make_float4(vlo[0], vlo[1], vlo[2], vlo[3]);
            *(float4*)(hb + j0 * 32 + a * 8 + 4)   = make_float4(vlo[4], vlo[5], vlo[6], vlo[7]);
            *(float4*)(hb + (j0 + 1) * 32 + a * 8)     = make_float4(vhi[0], vhi[1], vhi[2], vhi[3]);
            *(float4*)(hb + (j0 + 1) * 32 + a * 8 + 4) = make_float4(vhi[4], vhi[5], vhi[6], vhi[7]);
        }
        __syncwarp();
    }

    // layer 3 (two 64-col halves) + relu + max over K
    float* of = outfeat + (size_t)c * 128;
    const ull* b3u = (const ull*)b3;
#pragma unroll 1
    for (int h = 0; h < 2; h++) {
        ull acc[32];
#pragma unroll
        for (int jp = 0; jp < 4; jp++) {
            const ull bb = __ldg(b3u + h * 32 + 4 * bc + jp);
#pragma unroll
            for (int n = 0; n < 8; n++) acc[n * 4 + jp] = bb;
        }
        for (int i = 0; i < 64; i++) {
            float4 h0 = *(const float4*)(hb + i * 32 + a * 8);
            float4 h1 = *(const float4*)(hb + i * 32 + a * 8 + 4);
            ull w0_, w1_, w2_, w3_;
            LDSV2(w0_, w1_, w3a + i * 512 + h * 256 + bc * 32);
            LDSV2(w2_, w3_, w3a + i * 512 + h * 256 + bc * 32 + 16);
            OPROW(h0.x, 0);  OPROW(h0.y, 4);  OPROW(h0.z, 8);  OPROW(h0.w, 12);
            OPROW(h1.x, 16); OPROW(h1.y, 20); OPROW(h1.z, 24); OPROW(h1.w, 28);
        }
        float cm[8];
#pragma unroll
        for (int jp = 0; jp < 4; jp++) {
            float mlo = 0.f, mhi = 0.f;
#pragma unroll
            for (int n = 0; n < 8; n++) {
                float lo, hi; UNPACK2(lo, hi, acc[n * 4 + jp]);
                mlo = fmaxf(mlo, lo); mhi = fmaxf(mhi, hi);
            }
            cm[2 * jp] = mlo; cm[2 * jp + 1] = mhi;
        }
#pragma unroll
        for (int jj = 0; jj < 8; jj++) {
            cm[jj] = fmaxf(cm[jj], __shfl_xor_sync(0xffffffffu, cm[jj], 8));
            cm[jj] = fmaxf(cm[jj], __shfl_xor_sync(0xffffffffu, cm[jj], 16));
        }
        if (a == 0) {
            *(float4*)(of + h * 64 + bc * 8)     = make_float4(cm[0], cm[1], cm[2], cm[3]);
            *(float4*)(of + h * 64 + bc * 8 + 4) = make_float4(cm[4], cm[5], cm[6], cm[7]);
        }
    }
#undef OPROW
}

// ---------------------------------------------------------------------------
extern "C" void kernel_launch(void* const* d_in, const int* in_sizes, int n_in,
                              void* d_out, int out_size)
{
    (void)in_sizes; (void)n_in; (void)out_size;
    const float* xyz  = (const float*)d_in[0];
    const float* feat = (const float*)d_in[1];
    const float* W1   = (const float*)d_in[2];
    const float* b1   = (const float*)d_in[3];
    const float* W2   = (const float*)d_in[4];
    const float* b2   = (const float*)d_in[5];
    const float* W3   = (const float*)d_in[6];
    const float* b3   = (const float*)d_in[7];

    float* newxyz  = (float*)d_out;                       // [B,S,3]
    float* outfeat = newxyz + (size_t)BB * SS * 3;        // [B,S,128]

    cudaFuncSetAttribute(fps_kernel, cudaFuncAttributeMaxDynamicSharedMemorySize, 3 * NN * 4);
    cudaFuncSetAttribute(knn_kernel, cudaFuncAttributeMaxDynamicSharedMemorySize, CHUNK * 16);
    cudaFuncSetAttribute(mlp_kernel, cudaFuncAttributeMaxDynamicSharedMemorySize, 114688);

    pregemm_kernel<<<BB * NN / 256, 256>>>(feat, W1);
    fps_kernel<<<BB * FPS_CTAS, 256, 3 * NN * 4>>>(xyz, newxyz);
    knn_kernel<<<BB * SS / 16, 512, CHUNK * 16>>>(xyz, newxyz);
    mlp_kernel<<<BB * SS / 8, 256, 114688>>>(xyz, newxyz, W1, b1, W2, b2, W3, b3, outfeat);
}